// round 2
// baseline (speedup 1.0000x reference)
#include <cuda_runtime.h>
#include <cuda_bf16.h>
#include <cstdint>

#define MAX_N 50000
#define MAX_E 800000

// ---------------- device scratch (no allocation allowed) ----------------
__device__ float g_deg[MAX_N];
__device__ float g_dis[MAX_N];
__device__ float g_norm[MAX_E];
__device__ float g_h[(size_t)MAX_N * 128];   // GEMM output
__device__ float g_a[(size_t)MAX_N * 128];   // layer-1 activations
__device__ float g_b2[(size_t)MAX_N * 128];  // layer-2 activations

// ---------------- norm precompute ----------------
__global__ void k_deg_init(int N) {
    int i = blockIdx.x * blockDim.x + threadIdx.x;
    if (i < N) g_deg[i] = 1.0f;   // self-loop weight 1
}

__global__ void k_deg_edges(const int* __restrict__ dst, const float* __restrict__ w, int E) {
    int i = blockIdx.x * blockDim.x + threadIdx.x;
    if (i < E) atomicAdd(&g_deg[dst[i]], w[i]);
}

__global__ void k_dis(int N) {
    int i = blockIdx.x * blockDim.x + threadIdx.x;
    if (i < N) g_dis[i] = rsqrtf(g_deg[i]);   // deg >= 1 always
}

__global__ void k_edge_norm(const int* __restrict__ src, const int* __restrict__ dst,
                            const float* __restrict__ w, int E) {
    int i = blockIdx.x * blockDim.x + threadIdx.x;
    if (i < E) g_norm[i] = g_dis[src[i]] * w[i] * g_dis[dst[i]];
}

// ---------------- register-tiled fp32 GEMM: H[N,FO] = X[N,K] @ W[K,FO] ----------------
template<int K, int FO>
__global__ __launch_bounds__(256)
void k_gemm(const float* __restrict__ X, const float* __restrict__ W,
            float* __restrict__ H, int N) {
    constexpr int BM = 64, BK = 32;
    constexpr int TM = 4, TN = FO / 16;     // 16x16 thread grid
    __shared__ float Xs[BK][BM + 1];
    __shared__ float Ws[BK][FO];

    const int tid = threadIdx.x;
    const int tr = tid >> 4;     // 0..15
    const int tc = tid & 15;     // 0..15
    const int m0 = blockIdx.x * BM;

    float acc[TM][TN];
#pragma unroll
    for (int i = 0; i < TM; i++)
#pragma unroll
        for (int j = 0; j < TN; j++) acc[i][j] = 0.0f;

    for (int k0 = 0; k0 < K; k0 += BK) {
        // X tile: 64 x 32 floats = 512 float4, 2 per thread; store transposed
#pragma unroll
        for (int it = 0; it < 2; it++) {
            int f4 = tid + it * 256;
            int row = f4 >> 3;           // 8 float4 per row
            int kk = (f4 & 7) << 2;
            float4 v = make_float4(0.f, 0.f, 0.f, 0.f);
            int gr = m0 + row;
            if (gr < N) v = *(const float4*)(X + (size_t)gr * K + k0 + kk);
            Xs[kk + 0][row] = v.x;
            Xs[kk + 1][row] = v.y;
            Xs[kk + 2][row] = v.z;
            Xs[kk + 3][row] = v.w;
        }
        // W tile: 32 x FO floats
        constexpr int WF4 = BK * FO / 4;   // total float4
#pragma unroll
        for (int it = 0; it < WF4 / 256; it++) {
            int f4 = tid + it * 256;
            int row = f4 / (FO / 4);
            int cc = (f4 % (FO / 4)) << 2;
            *(float4*)&Ws[row][cc] = *(const float4*)(W + (size_t)(k0 + row) * FO + cc);
        }
        __syncthreads();

#pragma unroll
        for (int k = 0; k < BK; k++) {
            float rm[TM], rn[TN];
#pragma unroll
            for (int i = 0; i < TM; i++) rm[i] = Xs[k][tr * TM + i];
#pragma unroll
            for (int j = 0; j < TN; j++) rn[j] = Ws[k][tc * TN + j];
#pragma unroll
            for (int i = 0; i < TM; i++)
#pragma unroll
                for (int j = 0; j < TN; j++) acc[i][j] += rm[i] * rn[j];
        }
        __syncthreads();
    }

#pragma unroll
    for (int i = 0; i < TM; i++) {
        int gr = m0 + tr * TM + i;
        if (gr < N) {
#pragma unroll
            for (int j = 0; j < TN; j += 4) {
                *(float4*)(H + (size_t)gr * FO + tc * TN + j) =
                    make_float4(acc[i][j], acc[i][j + 1], acc[i][j + 2], acc[i][j + 3]);
            }
        }
    }
}

// ---------------- self-loop init + bias: A[i,:] = dis[i]^2 * H[i,:] + b ----------------
template<int FO>
__global__ void k_selfinit(const float* __restrict__ H, const float* __restrict__ bias,
                           float* __restrict__ A, int N) {
    constexpr int PR = FO / 4;
    int idx = blockIdx.x * blockDim.x + threadIdx.x;
    if (idx >= N * PR) return;
    int row = idx / PR;
    int c4 = (idx % PR) << 2;
    float d = g_dis[row];
    float sn = d * d;
    float4 h = *(const float4*)(H + (size_t)row * FO + c4);
    float4 b = *(const float4*)(bias + c4);
    float4 o = make_float4(fmaf(sn, h.x, b.x), fmaf(sn, h.y, b.y),
                           fmaf(sn, h.z, b.z), fmaf(sn, h.w, b.w));
    *(float4*)(A + (size_t)row * FO + c4) = o;
}

// ---------------- edge scatter: A[dst,:] += norm[e] * H[src,:] ----------------
__global__ __launch_bounds__(256)
void k_scatter128(const float* __restrict__ H, float* __restrict__ A,
                  const int* __restrict__ src, const int* __restrict__ dst, int E) {
    int e = (blockIdx.x * blockDim.x + threadIdx.x) >> 5;
    if (e >= E) return;
    int lane = threadIdx.x & 31;
    int s = __ldg(src + e);
    int d = __ldg(dst + e);
    float w = __ldg(g_norm + e);
    float4 v = *(const float4*)(H + (size_t)s * 128 + lane * 4);
    float* p = A + (size_t)d * 128 + lane * 4;
    asm volatile("red.global.add.v4.f32 [%0], {%1,%2,%3,%4};"
                 :: "l"(p), "f"(v.x * w), "f"(v.y * w), "f"(v.z * w), "f"(v.w * w)
                 : "memory");
}

__global__ __launch_bounds__(256)
void k_scatter64(const float* __restrict__ H, float* __restrict__ A,
                 const int* __restrict__ src, const int* __restrict__ dst, int E) {
    int e = (blockIdx.x * blockDim.x + threadIdx.x) >> 5;
    if (e >= E) return;
    int lane = threadIdx.x & 31;
    int s = __ldg(src + e);
    int d = __ldg(dst + e);
    float w = __ldg(g_norm + e);
    float2 v = *(const float2*)(H + (size_t)s * 64 + lane * 2);
    float* p = A + (size_t)d * 64 + lane * 2;
    asm volatile("red.global.add.v2.f32 [%0], {%1,%2};"
                 :: "l"(p), "f"(v.x * w), "f"(v.y * w)
                 : "memory");
}

// ---------------- in-place ReLU ----------------
__global__ void k_relu(float* __restrict__ A, int n4) {
    int i = blockIdx.x * blockDim.x + threadIdx.x;
    if (i >= n4) return;
    float4 v = *(const float4*)(A + (size_t)i * 4);
    v.x = fmaxf(v.x, 0.f); v.y = fmaxf(v.y, 0.f);
    v.z = fmaxf(v.z, 0.f); v.w = fmaxf(v.w, 0.f);
    *(float4*)(A + (size_t)i * 4) = v;
}

// ---------------- launch ----------------
extern "C" void kernel_launch(void* const* d_in, const int* in_sizes, int n_in,
                              void* d_out, int out_size) {
    const float* x  = (const float*)d_in[0];   // [N,256]
    const int*   ei = (const int*)d_in[1];     // [2,E]
    const float* ew = (const float*)d_in[2];   // [E]
    const float* W1 = (const float*)d_in[3];
    const float* b1 = (const float*)d_in[4];
    const float* W2 = (const float*)d_in[5];
    const float* b2 = (const float*)d_in[6];
    const float* W3 = (const float*)d_in[7];
    const float* b3 = (const float*)d_in[8];
    float* out = (float*)d_out;

    const int N = in_sizes[0] / 256;
    const int E = in_sizes[2];
    const int* src = ei;
    const int* dst = ei + E;

    float* gh;  cudaGetSymbolAddress((void**)&gh,  g_h);
    float* ga;  cudaGetSymbolAddress((void**)&ga,  g_a);
    float* gb;  cudaGetSymbolAddress((void**)&gb,  g_b2);

    const int T = 256;
    auto cdiv = [](int a, int b) { return (a + b - 1) / b; };

    // ---- normalization precompute ----
    k_deg_init<<<cdiv(N, T), T>>>(N);
    k_deg_edges<<<cdiv(E, T), T>>>(dst, ew, E);
    k_dis<<<cdiv(N, T), T>>>(N);
    k_edge_norm<<<cdiv(E, T), T>>>(src, dst, ew, E);

    const int gemm_blocks = cdiv(N, 64);
    const int scat_blocks = cdiv(E * 32, T);

    // ---- layer 1: 256 -> 128, ReLU ----
    k_gemm<256, 128><<<gemm_blocks, 256>>>(x, W1, gh, N);
    k_selfinit<128><<<cdiv(N * 32, T), T>>>(gh, b1, ga, N);
    k_scatter128<<<scat_blocks, T>>>(gh, ga, src, dst, E);
    k_relu<<<cdiv(N * 32, T), T>>>(ga, N * 32);

    // ---- layer 2: 128 -> 128, ReLU ----
    k_gemm<128, 128><<<gemm_blocks, 256>>>(ga, W2, gh, N);
    k_selfinit<128><<<cdiv(N * 32, T), T>>>(gh, b2, gb, N);
    k_scatter128<<<scat_blocks, T>>>(gh, gb, src, dst, E);
    k_relu<<<cdiv(N * 32, T), T>>>(gb, N * 32);

    // ---- layer 3: 128 -> 64, no activation, write d_out ----
    k_gemm<128, 64><<<gemm_blocks, 256>>>(gb, W3, gh, N);
    k_selfinit<64><<<cdiv(N * 16, T), T>>>(gh, b3, out, N);
    k_scatter64<<<scat_blocks, T>>>(gh, out, src, dst, E);
}

// round 3
// speedup vs baseline: 1.7894x; 1.7894x over previous
#include <cuda_runtime.h>
#include <cuda_bf16.h>
#include <cstdint>

#define MAX_N 50000
#define MAX_E 800000
#define CHUNK 256
#define MAX_CHUNKS ((MAX_N + CHUNK - 1) / CHUNK)

// ---------------- device scratch (no allocation allowed) ----------------
__device__ float g_deg[MAX_N];
__device__ float g_dis[MAX_N];
__device__ int   g_cnt[MAX_N];
__device__ int   g_rowptr[MAX_N + 1];
__device__ int   g_cur[MAX_N];
__device__ int   g_csum[MAX_CHUNKS];
__device__ int   g_esrc[MAX_E];
__device__ float g_eval[MAX_E];
__device__ float g_h[(size_t)MAX_N * 128];   // GEMM output
__device__ float g_a[(size_t)MAX_N * 128];   // layer-1 activations
__device__ float g_b2[(size_t)MAX_N * 128];  // layer-2 activations

// ---------------- precompute: degree + histogram ----------------
__global__ void k_init(int N) {
    int i = blockIdx.x * blockDim.x + threadIdx.x;
    if (i < N) { g_deg[i] = 1.0f; g_cnt[i] = 0; }
}

__global__ void k_hist(const int* __restrict__ dst, const float* __restrict__ w, int E) {
    int i = blockIdx.x * blockDim.x + threadIdx.x;
    if (i < E) {
        int d = dst[i];
        atomicAdd(&g_deg[d], w[i]);
        atomicAdd(&g_cnt[d], 1);
    }
}

__global__ void k_dis(int N) {
    int i = blockIdx.x * blockDim.x + threadIdx.x;
    if (i < N) g_dis[i] = rsqrtf(g_deg[i]);   // deg >= 1 always
}

// ---------------- two-level exclusive scan of g_cnt -> g_rowptr ----------------
__global__ void k_scanA(int N) {          // per-chunk exclusive scan + chunk totals
    __shared__ int s[CHUNK];
    int t = threadIdx.x;
    int i = blockIdx.x * CHUNK + t;
    int v = (i < N) ? g_cnt[i] : 0;
    s[t] = v;
    __syncthreads();
#pragma unroll
    for (int off = 1; off < CHUNK; off <<= 1) {
        int x = (t >= off) ? s[t - off] : 0;
        __syncthreads();
        s[t] += x;
        __syncthreads();
    }
    if (i < N) g_rowptr[i] = s[t] - v;     // chunk-local exclusive
    if (t == CHUNK - 1) g_csum[blockIdx.x] = s[t];
}

__global__ void k_scanB(int nchunks) {    // exclusive scan of chunk totals (single block)
    __shared__ int s[CHUNK];
    int t = threadIdx.x;
    int v = (t < nchunks) ? g_csum[t] : 0;
    s[t] = v;
    __syncthreads();
#pragma unroll
    for (int off = 1; off < CHUNK; off <<= 1) {
        int x = (t >= off) ? s[t - off] : 0;
        __syncthreads();
        s[t] += x;
        __syncthreads();
    }
    if (t < nchunks) g_csum[t] = s[t] - v;
}

__global__ void k_scanC(int N, int E) {   // add chunk offsets, seed fill cursors
    int i = blockIdx.x * blockDim.x + threadIdx.x;
    if (i < N) {
        int r = g_rowptr[i] + g_csum[i >> 8];
        g_rowptr[i] = r;
        g_cur[i] = r;
    }
    if (i == 0) g_rowptr[N] = E;
}

__global__ void k_fill(const int* __restrict__ src, const int* __restrict__ dst,
                       const float* __restrict__ w, int E) {
    int e = blockIdx.x * blockDim.x + threadIdx.x;
    if (e >= E) return;
    int d = dst[e];
    int s = src[e];
    int pos = atomicAdd(&g_cur[d], 1);
    g_esrc[pos] = s;
    g_eval[pos] = w[e] * g_dis[s];          // dis[dst] factored into epilogue
}

// ---------------- register-tiled fp32 GEMM: H[N,FO] = X[N,K] @ W[K,FO] ----------------
template<int K, int FO>
__global__ __launch_bounds__(256)
void k_gemm(const float* __restrict__ X, const float* __restrict__ W,
            float* __restrict__ H, int N) {
    constexpr int BM = 128, BK = 16;
    constexpr int TM = 8, TN = FO / 16;    // 16x16 thread grid
    __shared__ float Xs[BK][BM + 4];
    __shared__ float Ws[BK][FO];

    const int tid = threadIdx.x;
    const int tr = tid >> 4;     // 0..15
    const int tc = tid & 15;     // 0..15
    const int m0 = blockIdx.x * BM;

    float acc[TM][TN];
#pragma unroll
    for (int i = 0; i < TM; i++)
#pragma unroll
        for (int j = 0; j < TN; j++) acc[i][j] = 0.0f;

    for (int k0 = 0; k0 < K; k0 += BK) {
        // X tile: 128 rows x 16 cols = 512 float4, 2 per thread; store transposed
#pragma unroll
        for (int it = 0; it < 2; it++) {
            int f4 = tid + it * 256;
            int row = f4 >> 2;               // 4 float4 per row
            int kk = (f4 & 3) << 2;
            float4 v = make_float4(0.f, 0.f, 0.f, 0.f);
            int gr = m0 + row;
            if (gr < N) v = *(const float4*)(X + (size_t)gr * K + k0 + kk);
            Xs[kk + 0][row] = v.x;
            Xs[kk + 1][row] = v.y;
            Xs[kk + 2][row] = v.z;
            Xs[kk + 3][row] = v.w;
        }
        // W tile: 16 x FO floats
        constexpr int WF4 = BK * FO / 4;
#pragma unroll
        for (int it = 0; it < WF4 / 256; it++) {
            int f4 = tid + it * 256;
            int row = f4 / (FO / 4);
            int cc = (f4 % (FO / 4)) << 2;
            *(float4*)&Ws[row][cc] = *(const float4*)(W + (size_t)(k0 + row) * FO + cc);
        }
        __syncthreads();

#pragma unroll
        for (int k = 0; k < BK; k++) {
            float rm[TM], rn[TN];
#pragma unroll
            for (int i = 0; i < TM; i++) rm[i] = Xs[k][tr * TM + i];
#pragma unroll
            for (int j = 0; j < TN; j++) rn[j] = Ws[k][tc * TN + j];
#pragma unroll
            for (int i = 0; i < TM; i++)
#pragma unroll
                for (int j = 0; j < TN; j++) acc[i][j] += rm[i] * rn[j];
        }
        __syncthreads();
    }

#pragma unroll
    for (int i = 0; i < TM; i++) {
        int gr = m0 + tr * TM + i;
        if (gr < N) {
#pragma unroll
            for (int j = 0; j < TN; j += 4) {
                *(float4*)(H + (size_t)gr * FO + tc * TN + j) =
                    make_float4(acc[i][j], acc[i][j + 1], acc[i][j + 2], acc[i][j + 3]);
            }
        }
    }
}

// ---------------- fused CSR gather + self-loop + bias (+ReLU) ----------------
// out[d,:] = act( dis[d] * sum_e val_e * H[src_e,:] + dis[d]^2 * H[d,:] + b )
template<bool RELU>
__global__ __launch_bounds__(256)
void k_agg128(const float* __restrict__ H, const float* __restrict__ bias,
              float* __restrict__ Out, int N) {
    int node = (blockIdx.x * blockDim.x + threadIdx.x) >> 5;
    if (node >= N) return;
    int lane = threadIdx.x & 31;
    int beg = g_rowptr[node];
    int end = g_rowptr[node + 1];

    float4 acc = make_float4(0.f, 0.f, 0.f, 0.f);
    int j = beg;
    for (; j + 1 < end; j += 2) {
        int   s0 = __ldg(&g_esrc[j]);
        int   s1 = __ldg(&g_esrc[j + 1]);
        float v0 = __ldg(&g_eval[j]);
        float v1 = __ldg(&g_eval[j + 1]);
        float4 h0 = *(const float4*)(H + (size_t)s0 * 128 + lane * 4);
        float4 h1 = *(const float4*)(H + (size_t)s1 * 128 + lane * 4);
        acc.x += v0 * h0.x + v1 * h1.x;
        acc.y += v0 * h0.y + v1 * h1.y;
        acc.z += v0 * h0.z + v1 * h1.z;
        acc.w += v0 * h0.w + v1 * h1.w;
    }
    if (j < end) {
        int   s0 = __ldg(&g_esrc[j]);
        float v0 = __ldg(&g_eval[j]);
        float4 h0 = *(const float4*)(H + (size_t)s0 * 128 + lane * 4);
        acc.x += v0 * h0.x; acc.y += v0 * h0.y;
        acc.z += v0 * h0.z; acc.w += v0 * h0.w;
    }

    float d = g_dis[node];
    float dd = d * d;
    float4 hs = *(const float4*)(H + (size_t)node * 128 + lane * 4);
    float4 b = *(const float4*)(bias + lane * 4);
    float4 o;
    o.x = fmaf(d, acc.x, fmaf(dd, hs.x, b.x));
    o.y = fmaf(d, acc.y, fmaf(dd, hs.y, b.y));
    o.z = fmaf(d, acc.z, fmaf(dd, hs.z, b.z));
    o.w = fmaf(d, acc.w, fmaf(dd, hs.w, b.w));
    if (RELU) {
        o.x = fmaxf(o.x, 0.f); o.y = fmaxf(o.y, 0.f);
        o.z = fmaxf(o.z, 0.f); o.w = fmaxf(o.w, 0.f);
    }
    *(float4*)(Out + (size_t)node * 128 + lane * 4) = o;
}

__global__ __launch_bounds__(256)
void k_agg64(const float* __restrict__ H, const float* __restrict__ bias,
             float* __restrict__ Out, int N) {
    int node = (blockIdx.x * blockDim.x + threadIdx.x) >> 5;
    if (node >= N) return;
    int lane = threadIdx.x & 31;
    int beg = g_rowptr[node];
    int end = g_rowptr[node + 1];

    float2 acc = make_float2(0.f, 0.f);
    int j = beg;
    for (; j + 1 < end; j += 2) {
        int   s0 = __ldg(&g_esrc[j]);
        int   s1 = __ldg(&g_esrc[j + 1]);
        float v0 = __ldg(&g_eval[j]);
        float v1 = __ldg(&g_eval[j + 1]);
        float2 h0 = *(const float2*)(H + (size_t)s0 * 64 + lane * 2);
        float2 h1 = *(const float2*)(H + (size_t)s1 * 64 + lane * 2);
        acc.x += v0 * h0.x + v1 * h1.x;
        acc.y += v0 * h0.y + v1 * h1.y;
    }
    if (j < end) {
        int   s0 = __ldg(&g_esrc[j]);
        float v0 = __ldg(&g_eval[j]);
        float2 h0 = *(const float2*)(H + (size_t)s0 * 64 + lane * 2);
        acc.x += v0 * h0.x; acc.y += v0 * h0.y;
    }

    float d = g_dis[node];
    float dd = d * d;
    float2 hs = *(const float2*)(H + (size_t)node * 64 + lane * 2);
    float2 b = *(const float2*)(bias + lane * 2);
    float2 o;
    o.x = fmaf(d, acc.x, fmaf(dd, hs.x, b.x));
    o.y = fmaf(d, acc.y, fmaf(dd, hs.y, b.y));
    *(float2*)(Out + (size_t)node * 64 + lane * 2) = o;
}

// ---------------- launch ----------------
extern "C" void kernel_launch(void* const* d_in, const int* in_sizes, int n_in,
                              void* d_out, int out_size) {
    const float* x  = (const float*)d_in[0];   // [N,256]
    const int*   ei = (const int*)d_in[1];     // [2,E]
    const float* ew = (const float*)d_in[2];   // [E]
    const float* W1 = (const float*)d_in[3];
    const float* b1 = (const float*)d_in[4];
    const float* W2 = (const float*)d_in[5];
    const float* b2 = (const float*)d_in[6];
    const float* W3 = (const float*)d_in[7];
    const float* b3 = (const float*)d_in[8];
    float* out = (float*)d_out;

    const int N = in_sizes[0] / 256;
    const int E = in_sizes[2];
    const int* src = ei;
    const int* dst = ei + E;

    float* gh;  cudaGetSymbolAddress((void**)&gh,  g_h);
    float* ga;  cudaGetSymbolAddress((void**)&ga,  g_a);
    float* gb;  cudaGetSymbolAddress((void**)&gb,  g_b2);

    const int T = 256;
    auto cdiv = [](int a, int b) { return (a + b - 1) / b; };
    const int nchunks = cdiv(N, CHUNK);

    // ---- CSR + normalization precompute ----
    k_init<<<cdiv(N, T), T>>>(N);
    k_hist<<<cdiv(E, T), T>>>(dst, ew, E);
    k_dis<<<cdiv(N, T), T>>>(N);
    k_scanA<<<nchunks, CHUNK>>>(N);
    k_scanB<<<1, CHUNK>>>(nchunks);
    k_scanC<<<cdiv(N, T), T>>>(N, E);
    k_fill<<<cdiv(E, T), T>>>(src, dst, ew, E);

    const int gemm_blocks = cdiv(N, 128);
    const int agg_blocks = cdiv(N * 32, T);

    // ---- layer 1: 256 -> 128, ReLU ----
    k_gemm<256, 128><<<gemm_blocks, 256>>>(x, W1, gh, N);
    k_agg128<true><<<agg_blocks, T>>>(gh, b1, ga, N);

    // ---- layer 2: 128 -> 128, ReLU ----
    k_gemm<128, 128><<<gemm_blocks, 256>>>(ga, W2, gh, N);
    k_agg128<true><<<agg_blocks, T>>>(gh, b2, gb, N);

    // ---- layer 3: 128 -> 64, no activation, write d_out ----
    k_gemm<128, 64><<<gemm_blocks, 256>>>(gb, W3, gh, N);
    k_agg64<<<agg_blocks, T>>>(gh, b3, out, N);
}

// round 4
// speedup vs baseline: 1.9981x; 1.1167x over previous
#include <cuda_runtime.h>
#include <cuda_bf16.h>
#include <cstdint>

#define MAX_N 50000
#define MAX_E 800000
#define CHUNK 256
#define MAX_CHUNKS ((MAX_N + CHUNK - 1) / CHUNK)

// ---------------- device scratch (no allocation allowed) ----------------
__device__ float g_deg[MAX_N];
__device__ float g_dis[MAX_N];
__device__ int   g_cnt[MAX_N];
__device__ int   g_rowptr[MAX_N + 1];
__device__ int   g_cur[MAX_N];
__device__ int   g_csum[MAX_CHUNKS];
__device__ int   g_esrc[MAX_E];
__device__ float g_eval[MAX_E];
__device__ float g_h[(size_t)MAX_N * 128];   // GEMM output
__device__ float g_a[(size_t)MAX_N * 128];   // layer-1 activations
__device__ float g_b2[(size_t)MAX_N * 128];  // layer-2 activations

// ---------------- precompute: degree + histogram ----------------
__global__ void k_init(int N) {
    int i = blockIdx.x * blockDim.x + threadIdx.x;
    if (i < N) { g_deg[i] = 1.0f; g_cnt[i] = 0; }
}

__global__ void k_hist(const int* __restrict__ dst, const float* __restrict__ w, int E) {
    int i = blockIdx.x * blockDim.x + threadIdx.x;
    if (i < E) {
        int d = dst[i];
        atomicAdd(&g_deg[d], w[i]);
        atomicAdd(&g_cnt[d], 1);
    }
}

// ---------------- two-level exclusive scan of g_cnt -> g_rowptr ----------------
__global__ void k_scanA(int N) {
    __shared__ int s[CHUNK];
    int t = threadIdx.x;
    int i = blockIdx.x * CHUNK + t;
    int v = (i < N) ? g_cnt[i] : 0;
    s[t] = v;
    __syncthreads();
#pragma unroll
    for (int off = 1; off < CHUNK; off <<= 1) {
        int x = (t >= off) ? s[t - off] : 0;
        __syncthreads();
        s[t] += x;
        __syncthreads();
    }
    if (i < N) g_rowptr[i] = s[t] - v;
    if (t == CHUNK - 1) g_csum[blockIdx.x] = s[t];
}

__global__ void k_scanB(int nchunks) {
    __shared__ int s[CHUNK];
    int t = threadIdx.x;
    int v = (t < nchunks) ? g_csum[t] : 0;
    s[t] = v;
    __syncthreads();
#pragma unroll
    for (int off = 1; off < CHUNK; off <<= 1) {
        int x = (t >= off) ? s[t - off] : 0;
        __syncthreads();
        s[t] += x;
        __syncthreads();
    }
    if (t < nchunks) g_csum[t] = s[t] - v;
}

__global__ void k_scanC(int N, int E) {   // add chunk offsets, seed cursors, dis
    int i = blockIdx.x * blockDim.x + threadIdx.x;
    if (i < N) {
        int r = g_rowptr[i] + g_csum[i >> 8];
        g_rowptr[i] = r;
        g_cur[i] = r;
        g_dis[i] = rsqrtf(g_deg[i]);   // deg >= 1 always
    }
    if (i == 0) g_rowptr[N] = E;
}

__global__ void k_fill(const int* __restrict__ src, const int* __restrict__ dst,
                       const float* __restrict__ w, int E) {
    int e = blockIdx.x * blockDim.x + threadIdx.x;
    if (e >= E) return;
    int d = dst[e];
    int s = src[e];
    int pos = atomicAdd(&g_cur[d], 1);
    g_esrc[pos] = s;
    g_eval[pos] = w[e] * g_dis[s];          // dis[dst] factored into epilogue
}

// ---------------- 3xTF32 tensor-core GEMM: H[N,FO] = X[N,K] @ W[K,FO] ----------------
__device__ __forceinline__ uint32_t f2tf32(float x) {
    uint32_t r; asm("cvt.rna.tf32.f32 %0, %1;" : "=r"(r) : "f"(x)); return r;
}

__device__ __forceinline__ void split4(float4 v, float4& hi, float4& lo) {
    uint32_t hx = f2tf32(v.x), hy = f2tf32(v.y), hz = f2tf32(v.z), hw = f2tf32(v.w);
    hi = make_float4(__uint_as_float(hx), __uint_as_float(hy),
                     __uint_as_float(hz), __uint_as_float(hw));
    lo.x = __uint_as_float(f2tf32(v.x - hi.x));
    lo.y = __uint_as_float(f2tf32(v.y - hi.y));
    lo.z = __uint_as_float(f2tf32(v.z - hi.z));
    lo.w = __uint_as_float(f2tf32(v.w - hi.w));
}

__device__ __forceinline__ void mma_tf32(float* c, const uint32_t* a, const uint32_t* b) {
    asm volatile("mma.sync.aligned.m16n8k8.row.col.f32.tf32.tf32.f32 "
                 "{%0,%1,%2,%3}, {%4,%5,%6,%7}, {%8,%9}, {%0,%1,%2,%3};"
                 : "+f"(c[0]), "+f"(c[1]), "+f"(c[2]), "+f"(c[3])
                 : "r"(a[0]), "r"(a[1]), "r"(a[2]), "r"(a[3]),
                   "r"(b[0]), "r"(b[1]));
}

template<int K, int FO>
__global__ __launch_bounds__(256)
void k_gemm_tc(const float* __restrict__ X, const float* __restrict__ Wt,
               float* __restrict__ H, int N) {
    constexpr int BM = 128, BK = 32;
    constexpr int AP = BK + 4;            // 36-word row stride (conflict-free)
    constexpr int WP = FO + 8;            // conflict-free B-frag loads
    constexpr int NF = FO / 16;           // n-frags per warp (8 or 4)
    extern __shared__ float sm[];
    float* As_hi = sm;                    // [BM][AP]
    float* As_lo = As_hi + BM * AP;
    float* Ws_hi = As_lo + BM * AP;       // [BK][WP]
    float* Ws_lo = Ws_hi + BK * WP;

    const int tid = threadIdx.x;
    const int lane = tid & 31, wid = tid >> 5;
    const int g = lane >> 2, t = lane & 3;
    const int warp_m = (wid & 3) * 32;
    const int warp_n = (wid >> 2) * (FO / 2);
    const int m0 = blockIdx.x * BM;

    float acc[2][NF][4];
#pragma unroll
    for (int mf = 0; mf < 2; mf++)
#pragma unroll
        for (int nf = 0; nf < NF; nf++)
#pragma unroll
            for (int i = 0; i < 4; i++) acc[mf][nf][i] = 0.0f;

    for (int k0 = 0; k0 < K; k0 += BK) {
        // ---- A tile: 128x32 fp32, split into hi/lo tf32 ----
#pragma unroll
        for (int it = 0; it < 4; it++) {
            int f4 = tid + it * 256;
            int row = f4 >> 3;
            int kg = (f4 & 7) << 2;
            float4 v = make_float4(0.f, 0.f, 0.f, 0.f);
            if (m0 + row < N) v = *(const float4*)(X + (size_t)(m0 + row) * K + k0 + kg);
            float4 hi, lo;
            split4(v, hi, lo);
            *(float4*)(As_hi + row * AP + kg) = hi;
            *(float4*)(As_lo + row * AP + kg) = lo;
        }
        // ---- W tile: 32xFO fp32, split ----
        constexpr int WIT = BK * FO / 4 / 256;   // 4 (FO=128) or 2 (FO=64)
#pragma unroll
        for (int it = 0; it < WIT; it++) {
            int f4 = tid + it * 256;
            int row = f4 / (FO / 4);
            int c4 = (f4 % (FO / 4)) << 2;
            float4 v = *(const float4*)(Wt + (size_t)(k0 + row) * FO + c4);
            float4 hi, lo;
            split4(v, hi, lo);
            *(float4*)(Ws_hi + row * WP + c4) = hi;
            *(float4*)(Ws_lo + row * WP + c4) = lo;
        }
        __syncthreads();

#pragma unroll
        for (int ks = 0; ks < 4; ks++) {
            const int kb = ks * 8;
            uint32_t ah[2][4], al[2][4];
#pragma unroll
            for (int mf = 0; mf < 2; mf++) {
                const float* ph = As_hi + (warp_m + mf * 16 + g) * AP + kb;
                const float* pl = As_lo + (warp_m + mf * 16 + g) * AP + kb;
                ah[mf][0] = __float_as_uint(ph[t]);
                ah[mf][1] = __float_as_uint(ph[8 * AP + t]);
                ah[mf][2] = __float_as_uint(ph[t + 4]);
                ah[mf][3] = __float_as_uint(ph[8 * AP + t + 4]);
                al[mf][0] = __float_as_uint(pl[t]);
                al[mf][1] = __float_as_uint(pl[8 * AP + t]);
                al[mf][2] = __float_as_uint(pl[t + 4]);
                al[mf][3] = __float_as_uint(pl[8 * AP + t + 4]);
            }
#pragma unroll
            for (int nf = 0; nf < NF; nf++) {
                const int nb = warp_n + nf * 8 + g;
                const float* qh = Ws_hi + (kb + t) * WP + nb;
                const float* ql = Ws_lo + (kb + t) * WP + nb;
                uint32_t bh[2], bl[2];
                bh[0] = __float_as_uint(qh[0]);
                bh[1] = __float_as_uint(qh[4 * WP]);
                bl[0] = __float_as_uint(ql[0]);
                bl[1] = __float_as_uint(ql[4 * WP]);
#pragma unroll
                for (int mf = 0; mf < 2; mf++) {
                    mma_tf32(acc[mf][nf], ah[mf], bh);
                    mma_tf32(acc[mf][nf], al[mf], bh);
                    mma_tf32(acc[mf][nf], ah[mf], bl);
                }
            }
        }
        __syncthreads();
    }

    // ---- epilogue: direct global store ----
#pragma unroll
    for (int mf = 0; mf < 2; mf++) {
        int r0 = m0 + warp_m + mf * 16 + g;
#pragma unroll
        for (int nf = 0; nf < NF; nf++) {
            int col = warp_n + nf * 8 + 2 * t;
            if (r0 < N)
                *(float2*)(H + (size_t)r0 * FO + col) =
                    make_float2(acc[mf][nf][0], acc[mf][nf][1]);
            if (r0 + 8 < N)
                *(float2*)(H + (size_t)(r0 + 8) * FO + col) =
                    make_float2(acc[mf][nf][2], acc[mf][nf][3]);
        }
    }
}

// ---------------- fused CSR gather + self-loop + bias (+ReLU) ----------------
template<bool RELU>
__global__ __launch_bounds__(256)
void k_agg128(const float* __restrict__ H, const float* __restrict__ bias,
              float* __restrict__ Out, int N) {
    int node = (blockIdx.x * blockDim.x + threadIdx.x) >> 5;
    if (node >= N) return;
    int lane = threadIdx.x & 31;
    int beg = g_rowptr[node];
    int end = g_rowptr[node + 1];

    float4 acc = make_float4(0.f, 0.f, 0.f, 0.f);
    int j = beg;
    for (; j + 1 < end; j += 2) {
        int   s0 = __ldg(&g_esrc[j]);
        int   s1 = __ldg(&g_esrc[j + 1]);
        float v0 = __ldg(&g_eval[j]);
        float v1 = __ldg(&g_eval[j + 1]);
        float4 h0 = *(const float4*)(H + (size_t)s0 * 128 + lane * 4);
        float4 h1 = *(const float4*)(H + (size_t)s1 * 128 + lane * 4);
        acc.x += v0 * h0.x + v1 * h1.x;
        acc.y += v0 * h0.y + v1 * h1.y;
        acc.z += v0 * h0.z + v1 * h1.z;
        acc.w += v0 * h0.w + v1 * h1.w;
    }
    if (j < end) {
        int   s0 = __ldg(&g_esrc[j]);
        float v0 = __ldg(&g_eval[j]);
        float4 h0 = *(const float4*)(H + (size_t)s0 * 128 + lane * 4);
        acc.x += v0 * h0.x; acc.y += v0 * h0.y;
        acc.z += v0 * h0.z; acc.w += v0 * h0.w;
    }

    float d = g_dis[node];
    float dd = d * d;
    float4 hs = *(const float4*)(H + (size_t)node * 128 + lane * 4);
    float4 b = *(const float4*)(bias + lane * 4);
    float4 o;
    o.x = fmaf(d, acc.x, fmaf(dd, hs.x, b.x));
    o.y = fmaf(d, acc.y, fmaf(dd, hs.y, b.y));
    o.z = fmaf(d, acc.z, fmaf(dd, hs.z, b.z));
    o.w = fmaf(d, acc.w, fmaf(dd, hs.w, b.w));
    if (RELU) {
        o.x = fmaxf(o.x, 0.f); o.y = fmaxf(o.y, 0.f);
        o.z = fmaxf(o.z, 0.f); o.w = fmaxf(o.w, 0.f);
    }
    *(float4*)(Out + (size_t)node * 128 + lane * 4) = o;
}

__global__ __launch_bounds__(256)
void k_agg64(const float* __restrict__ H, const float* __restrict__ bias,
             float* __restrict__ Out, int N) {
    int node = (blockIdx.x * blockDim.x + threadIdx.x) >> 5;
    if (node >= N) return;
    int lane = threadIdx.x & 31;
    int beg = g_rowptr[node];
    int end = g_rowptr[node + 1];

    float2 acc = make_float2(0.f, 0.f);
    int j = beg;
    for (; j + 1 < end; j += 2) {
        int   s0 = __ldg(&g_esrc[j]);
        int   s1 = __ldg(&g_esrc[j + 1]);
        float v0 = __ldg(&g_eval[j]);
        float v1 = __ldg(&g_eval[j + 1]);
        float2 h0 = *(const float2*)(H + (size_t)s0 * 64 + lane * 2);
        float2 h1 = *(const float2*)(H + (size_t)s1 * 64 + lane * 2);
        acc.x += v0 * h0.x + v1 * h1.x;
        acc.y += v0 * h0.y + v1 * h1.y;
    }
    if (j < end) {
        int   s0 = __ldg(&g_esrc[j]);
        float v0 = __ldg(&g_eval[j]);
        float2 h0 = *(const float2*)(H + (size_t)s0 * 64 + lane * 2);
        acc.x += v0 * h0.x; acc.y += v0 * h0.y;
    }

    float d = g_dis[node];
    float dd = d * d;
    float2 hs = *(const float2*)(H + (size_t)node * 64 + lane * 2);
    float2 b = *(const float2*)(bias + lane * 2);
    float2 o;
    o.x = fmaf(d, acc.x, fmaf(dd, hs.x, b.x));
    o.y = fmaf(d, acc.y, fmaf(dd, hs.y, b.y));
    *(float2*)(Out + (size_t)node * 64 + lane * 2) = o;
}

// ---------------- launch ----------------
extern "C" void kernel_launch(void* const* d_in, const int* in_sizes, int n_in,
                              void* d_out, int out_size) {
    const float* x  = (const float*)d_in[0];   // [N,256]
    const int*   ei = (const int*)d_in[1];     // [2,E]
    const float* ew = (const float*)d_in[2];   // [E]
    const float* W1 = (const float*)d_in[3];
    const float* b1 = (const float*)d_in[4];
    const float* W2 = (const float*)d_in[5];
    const float* b2 = (const float*)d_in[6];
    const float* W3 = (const float*)d_in[7];
    const float* b3 = (const float*)d_in[8];
    float* out = (float*)d_out;

    const int N = in_sizes[0] / 256;
    const int E = in_sizes[2];
    const int* src = ei;
    const int* dst = ei + E;

    float* gh;  cudaGetSymbolAddress((void**)&gh,  g_h);
    float* ga;  cudaGetSymbolAddress((void**)&ga,  g_a);
    float* gb;  cudaGetSymbolAddress((void**)&gb,  g_b2);

    const int T = 256;
    auto cdiv = [](int a, int b) { return (a + b - 1) / b; };
    const int nchunks = cdiv(N, CHUNK);

    // dynamic smem sizes for the tensor-core GEMMs
    const int smem128 = (2 * 128 * 36 + 2 * 32 * 136) * 4;   // 71680 B
    const int smem64  = (2 * 128 * 36 + 2 * 32 * 72) * 4;    // 55296 B
    cudaFuncSetAttribute(k_gemm_tc<256, 128>, cudaFuncAttributeMaxDynamicSharedMemorySize, smem128);
    cudaFuncSetAttribute(k_gemm_tc<128, 128>, cudaFuncAttributeMaxDynamicSharedMemorySize, smem128);
    cudaFuncSetAttribute(k_gemm_tc<128, 64>,  cudaFuncAttributeMaxDynamicSharedMemorySize, smem64);

    // ---- CSR + normalization precompute ----
    k_init<<<cdiv(N, T), T>>>(N);
    k_hist<<<cdiv(E, T), T>>>(dst, ew, E);
    k_scanA<<<nchunks, CHUNK>>>(N);
    k_scanB<<<1, CHUNK>>>(nchunks);
    k_scanC<<<cdiv(N, T), T>>>(N, E);
    k_fill<<<cdiv(E, T), T>>>(src, dst, ew, E);

    const int gemm_blocks = cdiv(N, 128);
    const int agg_blocks = cdiv(N * 32, T);

    // ---- layer 1: 256 -> 128, ReLU ----
    k_gemm_tc<256, 128><<<gemm_blocks, 256, smem128>>>(x, W1, gh, N);
    k_agg128<true><<<agg_blocks, T>>>(gh, b1, ga, N);

    // ---- layer 2: 128 -> 128, ReLU ----
    k_gemm_tc<128, 128><<<gemm_blocks, 256, smem128>>>(ga, W2, gh, N);
    k_agg128<true><<<agg_blocks, T>>>(gh, b2, gb, N);

    // ---- layer 3: 128 -> 64, no activation, write d_out ----
    k_gemm_tc<128, 64><<<gemm_blocks, 256, smem64>>>(gb, W3, gh, N);
    k_agg64<<<agg_blocks, T>>>(gh, b3, out, N);
}

// round 7
// speedup vs baseline: 2.3614x; 1.1818x over previous
#include <cuda_runtime.h>
#include <cuda_bf16.h>
#include <cstdint>

#define MAX_N 50000
#define MAX_E 800000
#define CHUNK 256
#define MAX_CHUNKS ((MAX_N + CHUNK - 1) / CHUNK)

// ---------------- device scratch (no allocation allowed) ----------------
__device__ float g_deg[MAX_N];
__device__ float g_dis[MAX_N];
__device__ int   g_cnt[MAX_N];
__device__ int   g_rowptr[MAX_N + 1];
__device__ int   g_cur[MAX_N];
__device__ int   g_csum[MAX_CHUNKS];
__device__ int   g_esrc[MAX_E];
__device__ float g_eval[MAX_E];
__device__ float g_h[(size_t)MAX_N * 128];
__device__ float g_a[(size_t)MAX_N * 128];
__device__ float g_b2[(size_t)MAX_N * 128];
// pre-split transposed weights: [FO][K] layout, hi/lo tf32 parts
__device__ float g_w1hi[128 * 256], g_w1lo[128 * 256];
__device__ float g_w2hi[128 * 128], g_w2lo[128 * 128];
__device__ float g_w3hi[64 * 128],  g_w3lo[64 * 128];

// ---------------- tf32 helpers ----------------
__device__ __forceinline__ uint32_t f2tf32(float x) {
    uint32_t r; asm("cvt.rna.tf32.f32 %0, %1;" : "=r"(r) : "f"(x)); return r;
}

__device__ __forceinline__ void split4(float4 v, float4& hi, float4& lo) {
    hi.x = __uint_as_float(f2tf32(v.x));
    hi.y = __uint_as_float(f2tf32(v.y));
    hi.z = __uint_as_float(f2tf32(v.z));
    hi.w = __uint_as_float(f2tf32(v.w));
    lo.x = __uint_as_float(f2tf32(v.x - hi.x));
    lo.y = __uint_as_float(f2tf32(v.y - hi.y));
    lo.z = __uint_as_float(f2tf32(v.z - hi.z));
    lo.w = __uint_as_float(f2tf32(v.w - hi.w));
}

__device__ __forceinline__ void mma_tf32(float* c, const uint32_t* a, const uint32_t* b) {
    asm volatile("mma.sync.aligned.m16n8k8.row.col.f32.tf32.tf32.f32 "
                 "{%0,%1,%2,%3}, {%4,%5,%6,%7}, {%8,%9}, {%0,%1,%2,%3};"
                 : "+f"(c[0]), "+f"(c[1]), "+f"(c[2]), "+f"(c[3])
                 : "r"(a[0]), "r"(a[1]), "r"(a[2]), "r"(a[3]),
                   "r"(b[0]), "r"(b[1]));
}

__device__ __forceinline__ void ldsm_x4(uint32_t* r, uint32_t saddr) {
    asm volatile("ldmatrix.sync.aligned.m8n8.x4.shared.b16 {%0,%1,%2,%3}, [%4];"
                 : "=r"(r[0]), "=r"(r[1]), "=r"(r[2]), "=r"(r[3]) : "r"(saddr));
}

__device__ __forceinline__ void ldsm_x2(uint32_t* r, uint32_t saddr) {
    asm volatile("ldmatrix.sync.aligned.m8n8.x2.shared.b16 {%0,%1}, [%2];"
                 : "=r"(r[0]), "=r"(r[1]) : "r"(saddr));
}

// ---------------- weight pre-split (transposed) ----------------
__global__ void k_splitW(const float* __restrict__ W1, const float* __restrict__ W2,
                         const float* __restrict__ W3) {
    int i = blockIdx.x * blockDim.x + threadIdx.x;
    const int n1 = 256 * 128, n2 = 128 * 128, n3 = 128 * 64;
    float v; float* ph; float* pl;
    if (i < n1) {
        int k = i / 128, n = i % 128;
        v = W1[i]; ph = &g_w1hi[n * 256 + k]; pl = &g_w1lo[n * 256 + k];
    } else if (i < n1 + n2) {
        int j = i - n1; int k = j / 128, n = j % 128;
        v = W2[j]; ph = &g_w2hi[n * 128 + k]; pl = &g_w2lo[n * 128 + k];
    } else if (i < n1 + n2 + n3) {
        int j = i - n1 - n2; int k = j / 64, n = j % 64;
        v = W3[j]; ph = &g_w3hi[n * 128 + k]; pl = &g_w3lo[n * 128 + k];
    } else return;
    float hi = __uint_as_float(f2tf32(v));
    *ph = hi;
    *pl = __uint_as_float(f2tf32(v - hi));
}

// ---------------- CSR precompute ----------------
__global__ void k_hist(const int* __restrict__ dst, const float* __restrict__ w, int E) {
    int i = blockIdx.x * blockDim.x + threadIdx.x;
    if (i < E) {
        int d = dst[i];
        atomicAdd(&g_deg[d], w[i]);
        atomicAdd(&g_cnt[d], 1);
    }
}

__global__ void k_scanA(int N) {
    __shared__ int s[CHUNK];
    int t = threadIdx.x;
    int i = blockIdx.x * CHUNK + t;
    int v = (i < N) ? g_cnt[i] : 0;
    s[t] = v;
    __syncthreads();
#pragma unroll
    for (int off = 1; off < CHUNK; off <<= 1) {
        int x = (t >= off) ? s[t - off] : 0;
        __syncthreads();
        s[t] += x;
        __syncthreads();
    }
    if (i < N) g_rowptr[i] = s[t] - v;
    if (t == CHUNK - 1) g_csum[blockIdx.x] = s[t];
}

__global__ void k_scanC(int N, int E, int nchunks) {
    __shared__ int sc[CHUNK];
    int t = threadIdx.x;
    int v = (t < nchunks) ? g_csum[t] : 0;
    sc[t] = v;
    __syncthreads();
#pragma unroll
    for (int off = 1; off < CHUNK; off <<= 1) {
        int x = (t >= off) ? sc[t - off] : 0;
        __syncthreads();
        sc[t] += x;
        __syncthreads();
    }
    int i = blockIdx.x * blockDim.x + t;
    if (i < N) {
        int c = i >> 8;
        int off = (c == 0) ? 0 : sc[c - 1];
        int r = g_rowptr[i] + off;
        g_rowptr[i] = r;
        g_cur[i] = r;
        g_dis[i] = rsqrtf(g_deg[i] + 1.0f);   // self-loop weight 1
    }
    if (i == 0) g_rowptr[N] = E;
}

__global__ void k_fill(const int* __restrict__ src, const int* __restrict__ dst,
                       const float* __restrict__ w, int E) {
    int e = blockIdx.x * blockDim.x + threadIdx.x;
    if (e >= E) return;
    int d = dst[e];
    int s = src[e];
    int pos = atomicAdd(&g_cur[d], 1);
    g_esrc[pos] = s;
    g_eval[pos] = w[e] * g_dis[s];
}

// ---------------- 3xTF32 tensor-core GEMM with ldmatrix ----------------
// H[N,FO] = X[N,K] @ W[K,FO]; W provided pre-split transposed hi/lo [FO][K]
template<int K, int FO>
__global__ __launch_bounds__(256)
void k_gemm_tc(const float* __restrict__ X,
               const float* __restrict__ Whi_t, const float* __restrict__ Wlo_t,
               float* __restrict__ H, int N) {
    constexpr int BM = 128, BK = 32;
    constexpr int AP = BK + 4;            // 36-float row stride
    constexpr int NF = FO / 16;
    extern __shared__ float sm[];
    float* As_hi = sm;                    // [BM][AP]
    float* As_lo = As_hi + BM * AP;
    float* Ws_hi = As_lo + BM * AP;       // [FO][AP]  (n-major)
    float* Ws_lo = Ws_hi + FO * AP;

    const int tid = threadIdx.x;
    const int lane = tid & 31, wid = tid >> 5;
    const int g = lane >> 2, t = lane & 3;
    const int warp_m = (wid & 3) * 32;
    const int warp_n = (wid >> 2) * (FO / 2);
    const int m0 = blockIdx.x * BM;

    const uint32_t as_hi_b = (uint32_t)__cvta_generic_to_shared(As_hi);
    const uint32_t as_lo_b = (uint32_t)__cvta_generic_to_shared(As_lo);
    const uint32_t ws_hi_b = (uint32_t)__cvta_generic_to_shared(Ws_hi);
    const uint32_t ws_lo_b = (uint32_t)__cvta_generic_to_shared(Ws_lo);

    // ldmatrix lane-address components
    const int a_grp = lane >> 3, a_r8 = lane & 7;              // x4
    const int b_r8 = lane & 7, b_half = (lane >> 3) & 1;       // x2 (lanes 0-15)

    float acc[2][NF][4];
#pragma unroll
    for (int mf = 0; mf < 2; mf++)
#pragma unroll
        for (int nf = 0; nf < NF; nf++)
#pragma unroll
            for (int i = 0; i < 4; i++) acc[mf][nf][i] = 0.0f;

    for (int k0 = 0; k0 < K; k0 += BK) {
        // ---- A tile: 128x32 fp32 -> hi/lo tf32 ----
#pragma unroll
        for (int it = 0; it < 4; it++) {
            int f4 = tid + it * 256;
            int row = f4 >> 3;
            int kg = (f4 & 7) << 2;
            float4 v = make_float4(0.f, 0.f, 0.f, 0.f);
            if (m0 + row < N) v = *(const float4*)(X + (size_t)(m0 + row) * K + k0 + kg);
            float4 hi, lo;
            split4(v, hi, lo);
            *(float4*)(As_hi + row * AP + kg) = hi;
            *(float4*)(As_lo + row * AP + kg) = lo;
        }
        // ---- W tile: [FO][BK] from transposed pre-split globals ----
        constexpr int WIT = FO * BK / 4 / 256;   // 4 (FO=128) or 2 (FO=64)
#pragma unroll
        for (int it = 0; it < WIT; it++) {
            int f4 = tid + it * 256;
            int n = f4 >> 3;
            int kg = (f4 & 7) << 2;
            *(float4*)(Ws_hi + n * AP + kg) = *(const float4*)(Whi_t + (size_t)n * K + k0 + kg);
            *(float4*)(Ws_lo + n * AP + kg) = *(const float4*)(Wlo_t + (size_t)n * K + k0 + kg);
        }
        __syncthreads();

#pragma unroll
        for (int ks = 0; ks < 4; ks++) {
            const int kb = ks * 8;
            uint32_t ah[2][4], al[2][4];
#pragma unroll
            for (int mf = 0; mf < 2; mf++) {
                uint32_t off = ((warp_m + mf * 16 + (a_grp & 1) * 8 + a_r8) * AP
                                + kb + (a_grp >> 1) * 4) * 4;
                ldsm_x4(ah[mf], as_hi_b + off);
                ldsm_x4(al[mf], as_lo_b + off);
            }
#pragma unroll
            for (int nf = 0; nf < NF; nf++) {
                uint32_t boff = ((warp_n + nf * 8 + b_r8) * AP + kb + b_half * 4) * 4;
                uint32_t bh[2], bl[2];
                ldsm_x2(bh, ws_hi_b + boff);
                ldsm_x2(bl, ws_lo_b + boff);
#pragma unroll
                for (int mf = 0; mf < 2; mf++) {
                    mma_tf32(acc[mf][nf], ah[mf], bh);
                    mma_tf32(acc[mf][nf], al[mf], bh);
                    mma_tf32(acc[mf][nf], ah[mf], bl);
                }
            }
        }
        __syncthreads();
    }

#pragma unroll
    for (int mf = 0; mf < 2; mf++) {
        int r0 = m0 + warp_m + mf * 16 + g;
#pragma unroll
        for (int nf = 0; nf < NF; nf++) {
            int col = warp_n + nf * 8 + 2 * t;
            if (r0 < N)
                *(float2*)(H + (size_t)r0 * FO + col) =
                    make_float2(acc[mf][nf][0], acc[mf][nf][1]);
            if (r0 + 8 < N)
                *(float2*)(H + (size_t)(r0 + 8) * FO + col) =
                    make_float2(acc[mf][nf][2], acc[mf][nf][3]);
        }
    }
}

// ---------------- fused CSR gather + self-loop + bias (+ReLU) ----------------
template<bool RELU>
__global__ __launch_bounds__(256)
void k_agg128(const float* __restrict__ H, const float* __restrict__ bias,
              float* __restrict__ Out, int N) {
    int node = (blockIdx.x * blockDim.x + threadIdx.x) >> 5;
    if (node >= N) return;
    int lane = threadIdx.x & 31;
    int beg = g_rowptr[node];
    int end = g_rowptr[node + 1];

    float4 acc = make_float4(0.f, 0.f, 0.f, 0.f);
    int j = beg;
    for (; j + 1 < end; j += 2) {
        int   s0 = __ldg(&g_esrc[j]);
        int   s1 = __ldg(&g_esrc[j + 1]);
        float v0 = __ldg(&g_eval[j]);
        float v1 = __ldg(&g_eval[j + 1]);
        float4 h0 = *(const float4*)(H + (size_t)s0 * 128 + lane * 4);
        float4 h1 = *(const float4*)(H + (size_t)s1 * 128 + lane * 4);
        acc.x += v0 * h0.x + v1 * h1.x;
        acc.y += v0 * h0.y + v1 * h1.y;
        acc.z += v0 * h0.z + v1 * h1.z;
        acc.w += v0 * h0.w + v1 * h1.w;
    }
    if (j < end) {
        int   s0 = __ldg(&g_esrc[j]);
        float v0 = __ldg(&g_eval[j]);
        float4 h0 = *(const float4*)(H + (size_t)s0 * 128 + lane * 4);
        acc.x += v0 * h0.x; acc.y += v0 * h0.y;
        acc.z += v0 * h0.z; acc.w += v0 * h0.w;
    }

    float d = g_dis[node];
    float dd = d * d;
    float4 hs = *(const float4*)(H + (size_t)node * 128 + lane * 4);
    float4 b = *(const float4*)(bias + lane * 4);
    float4 o;
    o.x = fmaf(d, acc.x, fmaf(dd, hs.x, b.x));
    o.y = fmaf(d, acc.y, fmaf(dd, hs.y, b.y));
    o.z = fmaf(d, acc.z, fmaf(dd, hs.z, b.z));
    o.w = fmaf(d, acc.w, fmaf(dd, hs.w, b.w));
    if (RELU) {
        o.x = fmaxf(o.x, 0.f); o.y = fmaxf(o.y, 0.f);
        o.z = fmaxf(o.z, 0.f); o.w = fmaxf(o.w, 0.f);
    }
    *(float4*)(Out + (size_t)node * 128 + lane * 4) = o;
}

__global__ __launch_bounds__(256)
void k_agg64(const float* __restrict__ H, const float* __restrict__ bias,
             float* __restrict__ Out, int N) {
    int node = (blockIdx.x * blockDim.x + threadIdx.x) >> 5;
    if (node >= N) return;
    int lane = threadIdx.x & 31;
    int beg = g_rowptr[node];
    int end = g_rowptr[node + 1];

    float2 acc = make_float2(0.f, 0.f);
    int j = beg;
    for (; j + 1 < end; j += 2) {
        int   s0 = __ldg(&g_esrc[j]);
        int   s1 = __ldg(&g_esrc[j + 1]);
        float v0 = __ldg(&g_eval[j]);
        float v1 = __ldg(&g_eval[j + 1]);
        float2 h0 = *(const float2*)(H + (size_t)s0 * 64 + lane * 2);
        float2 h1 = *(const float2*)(H + (size_t)s1 * 64 + lane * 2);
        acc.x += v0 * h0.x + v1 * h1.x;
        acc.y += v0 * h0.y + v1 * h1.y;
    }
    if (j < end) {
        int   s0 = __ldg(&g_esrc[j]);
        float v0 = __ldg(&g_eval[j]);
        float2 h0 = *(const float2*)(H + (size_t)s0 * 64 + lane * 2);
        acc.x += v0 * h0.x; acc.y += v0 * h0.y;
    }

    float d = g_dis[node];
    float dd = d * d;
    float2 hs = *(const float2*)(H + (size_t)node * 64 + lane * 2);
    float2 b = *(const float2*)(bias + lane * 2);
    float2 o;
    o.x = fmaf(d, acc.x, fmaf(dd, hs.x, b.x));
    o.y = fmaf(d, acc.y, fmaf(dd, hs.y, b.y));
    *(float2*)(Out + (size_t)node * 64 + lane * 2) = o;
}

// ---------------- launch ----------------
extern "C" void kernel_launch(void* const* d_in, const int* in_sizes, int n_in,
                              void* d_out, int out_size) {
    const float* x  = (const float*)d_in[0];
    const int*   ei = (const int*)d_in[1];
    const float* ew = (const float*)d_in[2];
    const float* W1 = (const float*)d_in[3];
    const float* b1 = (const float*)d_in[4];
    const float* W2 = (const float*)d_in[5];
    const float* b2 = (const float*)d_in[6];
    const float* W3 = (const float*)d_in[7];
    const float* b3 = (const float*)d_in[8];
    float* out = (float*)d_out;

    const int N = in_sizes[0] / 256;
    const int E = in_sizes[2];
    const int* src = ei;
    const int* dst = ei + E;

    float* gh;  cudaGetSymbolAddress((void**)&gh,  g_h);
    float* ga;  cudaGetSymbolAddress((void**)&ga,  g_a);
    float* gb;  cudaGetSymbolAddress((void**)&gb,  g_b2);
    float* gdeg; cudaGetSymbolAddress((void**)&gdeg, g_deg);
    int*   gcnt; cudaGetSymbolAddress((void**)&gcnt, g_cnt);
    float* w1h; cudaGetSymbolAddress((void**)&w1h, g_w1hi);
    float* w1l; cudaGetSymbolAddress((void**)&w1l, g_w1lo);
    float* w2h; cudaGetSymbolAddress((void**)&w2h, g_w2hi);
    float* w2l; cudaGetSymbolAddress((void**)&w2l, g_w2lo);
    float* w3h; cudaGetSymbolAddress((void**)&w3h, g_w3hi);
    float* w3l; cudaGetSymbolAddress((void**)&w3l, g_w3lo);

    const int T = 256;
    auto cdiv = [](int a, int b) { return (a + b - 1) / b; };
    const int nchunks = cdiv(N, CHUNK);

    const int smem128 = (2 * 128 * 36 + 2 * 128 * 36) * 4;   // 73728 B
    const int smem64  = (2 * 128 * 36 + 2 * 64 * 36) * 4;    // 55296 B
    cudaFuncSetAttribute(k_gemm_tc<256, 128>, cudaFuncAttributeMaxDynamicSharedMemorySize, smem128);
    cudaFuncSetAttribute(k_gemm_tc<128, 128>, cudaFuncAttributeMaxDynamicSharedMemorySize, smem128);
    cudaFuncSetAttribute(k_gemm_tc<128, 64>,  cudaFuncAttributeMaxDynamicSharedMemorySize, smem64);

    // side stream + events, created once outside any capture (first call is the
    // correctness run; capture happens on a later call and re-records the fork).
    static cudaStream_t s2 = nullptr;
    static cudaEvent_t evF = nullptr, evJ = nullptr;
    if (s2 == nullptr) {
        cudaStreamCreateWithFlags(&s2, cudaStreamNonBlocking);
        cudaEventCreateWithFlags(&evF, cudaEventDisableTiming);
        cudaEventCreateWithFlags(&evJ, cudaEventDisableTiming);
    }

    // ---- fork: CSR build on s2, weights+GEMM1 on default ----
    cudaEventRecord(evF, 0);
    cudaStreamWaitEvent(s2, evF, 0);

    cudaMemsetAsync(gdeg, 0, N * sizeof(float), s2);
    cudaMemsetAsync(gcnt, 0, N * sizeof(int), s2);
    k_hist<<<cdiv(E, T), T, 0, s2>>>(dst, ew, E);
    k_scanA<<<nchunks, CHUNK, 0, s2>>>(N);
    k_scanC<<<cdiv(N, T), T, 0, s2>>>(N, E, nchunks);
    k_fill<<<cdiv(E, T), T, 0, s2>>>(src, dst, ew, E);

    const int wtot = 256 * 128 + 128 * 128 + 128 * 64;
    k_splitW<<<cdiv(wtot, T), T>>>(W1, W2, W3);

    const int gemm_blocks = cdiv(N, 128);
    const int agg_blocks = cdiv(N * 32, T);

    k_gemm_tc<256, 128><<<gemm_blocks, 256, smem128>>>(x, w1h, w1l, gh, N);

    // ---- join ----
    cudaEventRecord(evJ, s2);
    cudaStreamWaitEvent(0, evJ, 0);

    k_agg128<true><<<agg_blocks, T>>>(gh, b1, ga, N);

    k_gemm_tc<128, 128><<<gemm_blocks, 256, smem128>>>(ga, w2h, w2l, gh, N);
    k_agg128<true><<<agg_blocks, T>>>(gh, b2, gb, N);

    k_gemm_tc<128, 64><<<gemm_blocks, 256, smem64>>>(gb, w3h, w3l, gh, N);
    k_agg64<<<agg_blocks, T>>>(gh, b3, out, N);
}

// round 10
// speedup vs baseline: 2.4469x; 1.0362x over previous
#include <cuda_runtime.h>
#include <cuda_bf16.h>
#include <cuda_fp16.h>
#include <cstdint>

#define MAX_N 50000
#define MAX_E 800000
#define CHUNK 256
#define MAX_CHUNKS ((MAX_N + CHUNK - 1) / CHUNK)

// ---------------- device scratch (no allocation allowed) ----------------
__device__ float g_deg[MAX_N];
__device__ float g_dis[MAX_N];
__device__ int   g_cnt[MAX_N];
__device__ int   g_rowptr[MAX_N + 1];
__device__ int   g_cur[MAX_N];
__device__ int   g_csum[MAX_CHUNKS];
__device__ int2  g_epack[MAX_E];                 // (src, val bits)
__device__ __half g_hh[(size_t)MAX_N * 128];     // fp16 GEMM output (layers 1-2)
__device__ float g_h[(size_t)MAX_N * 128];       // fp32 GEMM output (layer 3)
__device__ float g_a[(size_t)MAX_N * 128];
__device__ float g_b2[(size_t)MAX_N * 128];
// pre-split transposed weights: [FO][K] layout, hi/lo tf32 parts
__device__ float g_w1hi[128 * 256], g_w1lo[128 * 256];
__device__ float g_w2hi[128 * 128], g_w2lo[128 * 128];
__device__ float g_w3hi[64 * 128],  g_w3lo[64 * 128];

// ---------------- tf32 helpers ----------------
__device__ __forceinline__ uint32_t f2tf32(float x) {
    uint32_t r; asm("cvt.rna.tf32.f32 %0, %1;" : "=r"(r) : "f"(x)); return r;
}

__device__ __forceinline__ void split4(float4 v, float4& hi, float4& lo) {
    hi.x = __uint_as_float(f2tf32(v.x));
    hi.y = __uint_as_float(f2tf32(v.y));
    hi.z = __uint_as_float(f2tf32(v.z));
    hi.w = __uint_as_float(f2tf32(v.w));
    lo.x = __uint_as_float(f2tf32(v.x - hi.x));
    lo.y = __uint_as_float(f2tf32(v.y - hi.y));
    lo.z = __uint_as_float(f2tf32(v.z - hi.z));
    lo.w = __uint_as_float(f2tf32(v.w - hi.w));
}

__device__ __forceinline__ void mma_tf32(float* c, const uint32_t* a, const uint32_t* b) {
    asm volatile("mma.sync.aligned.m16n8k8.row.col.f32.tf32.tf32.f32 "
                 "{%0,%1,%2,%3}, {%4,%5,%6,%7}, {%8,%9}, {%0,%1,%2,%3};"
                 : "+f"(c[0]), "+f"(c[1]), "+f"(c[2]), "+f"(c[3])
                 : "r"(a[0]), "r"(a[1]), "r"(a[2]), "r"(a[3]),
                   "r"(b[0]), "r"(b[1]));
}

__device__ __forceinline__ void ldsm_x4(uint32_t* r, uint32_t saddr) {
    asm volatile("ldmatrix.sync.aligned.m8n8.x4.shared.b16 {%0,%1,%2,%3}, [%4];"
                 : "=r"(r[0]), "=r"(r[1]), "=r"(r[2]), "=r"(r[3]) : "r"(saddr));
}

__device__ __forceinline__ void ldsm_x2(uint32_t* r, uint32_t saddr) {
    asm volatile("ldmatrix.sync.aligned.m8n8.x2.shared.b16 {%0,%1}, [%2];"
                 : "=r"(r[0]), "=r"(r[1]) : "r"(saddr));
}

// ---------------- weight pre-split (transposed) ----------------
__global__ void k_splitW(const float* __restrict__ W1, const float* __restrict__ W2,
                         const float* __restrict__ W3) {
    int i = blockIdx.x * blockDim.x + threadIdx.x;
    const int n1 = 256 * 128, n2 = 128 * 128, n3 = 128 * 64;
    float v; float* ph; float* pl;
    if (i < n1) {
        int k = i / 128, n = i % 128;
        v = W1[i]; ph = &g_w1hi[n * 256 + k]; pl = &g_w1lo[n * 256 + k];
    } else if (i < n1 + n2) {
        int j = i - n1; int k = j / 128, n = j % 128;
        v = W2[j]; ph = &g_w2hi[n * 128 + k]; pl = &g_w2lo[n * 128 + k];
    } else if (i < n1 + n2 + n3) {
        int j = i - n1 - n2; int k = j / 64, n = j % 64;
        v = W3[j]; ph = &g_w3hi[n * 128 + k]; pl = &g_w3lo[n * 128 + k];
    } else return;
    float hi = __uint_as_float(f2tf32(v));
    *ph = hi;
    *pl = __uint_as_float(f2tf32(v - hi));
}

// ---------------- CSR precompute ----------------
__global__ void k_hist(const int* __restrict__ dst, const float* __restrict__ w, int E) {
    int i = blockIdx.x * blockDim.x + threadIdx.x;
    if (i < E) {
        int d = dst[i];
        atomicAdd(&g_deg[d], w[i]);
        atomicAdd(&g_cnt[d], 1);
    }
}

__global__ void k_scanA(int N) {
    __shared__ int s[CHUNK];
    int t = threadIdx.x;
    int i = blockIdx.x * CHUNK + t;
    int v = (i < N) ? g_cnt[i] : 0;
    s[t] = v;
    __syncthreads();
#pragma unroll
    for (int off = 1; off < CHUNK; off <<= 1) {
        int x = (t >= off) ? s[t - off] : 0;
        __syncthreads();
        s[t] += x;
        __syncthreads();
    }
    if (i < N) g_rowptr[i] = s[t] - v;
    if (t == CHUNK - 1) g_csum[blockIdx.x] = s[t];
}

__global__ void k_scanC(int N, int E, int nchunks) {
    __shared__ int sc[CHUNK];
    int t = threadIdx.x;
    int v = (t < nchunks) ? g_csum[t] : 0;
    sc[t] = v;
    __syncthreads();
#pragma unroll
    for (int off = 1; off < CHUNK; off <<= 1) {
        int x = (t >= off) ? sc[t - off] : 0;
        __syncthreads();
        sc[t] += x;
        __syncthreads();
    }
    int i = blockIdx.x * blockDim.x + t;
    if (i < N) {
        int c = i >> 8;
        int off = (c == 0) ? 0 : sc[c - 1];
        int r = g_rowptr[i] + off;
        g_rowptr[i] = r;
        g_cur[i] = r;
        g_dis[i] = rsqrtf(g_deg[i] + 1.0f);   // self-loop weight 1
    }
    if (i == 0) g_rowptr[N] = E;
}

__global__ void k_fill(const int* __restrict__ src, const int* __restrict__ dst,
                       const float* __restrict__ w, int E) {
    int e = blockIdx.x * blockDim.x + threadIdx.x;
    if (e >= E) return;
    int d = dst[e];
    int s = src[e];
    int pos = atomicAdd(&g_cur[d], 1);
    int2 pk;
    pk.x = s;
    pk.y = __float_as_int(w[e] * g_dis[s]);   // dis[dst] factored into epilogue
    g_epack[pos] = pk;
}

// ---------------- 3xTF32 tensor-core GEMM with ldmatrix ----------------
// H[N,FO] = X[N,K] @ W[K,FO]; W pre-split transposed hi/lo [FO][K]
// H16: store output as __half
template<int K, int FO, bool H16>
__global__ __launch_bounds__(256)
void k_gemm_tc(const float* __restrict__ X,
               const float* __restrict__ Whi_t, const float* __restrict__ Wlo_t,
               void* __restrict__ Hout, int N) {
    constexpr int BM = 128, BK = 32;
    constexpr int AP = BK + 4;
    constexpr int NF = FO / 16;
    extern __shared__ float sm[];
    float* As_hi = sm;
    float* As_lo = As_hi + BM * AP;
    float* Ws_hi = As_lo + BM * AP;
    float* Ws_lo = Ws_hi + FO * AP;

    const int tid = threadIdx.x;
    const int lane = tid & 31, wid = tid >> 5;
    const int g = lane >> 2, t = lane & 3;
    const int warp_m = (wid & 3) * 32;
    const int warp_n = (wid >> 2) * (FO / 2);
    const int m0 = blockIdx.x * BM;

    const uint32_t as_hi_b = (uint32_t)__cvta_generic_to_shared(As_hi);
    const uint32_t as_lo_b = (uint32_t)__cvta_generic_to_shared(As_lo);
    const uint32_t ws_hi_b = (uint32_t)__cvta_generic_to_shared(Ws_hi);
    const uint32_t ws_lo_b = (uint32_t)__cvta_generic_to_shared(Ws_lo);

    const int a_grp = lane >> 3, a_r8 = lane & 7;
    const int b_r8 = lane & 7, b_half = (lane >> 3) & 1;

    float acc[2][NF][4];
#pragma unroll
    for (int mf = 0; mf < 2; mf++)
#pragma unroll
        for (int nf = 0; nf < NF; nf++)
#pragma unroll
            for (int i = 0; i < 4; i++) acc[mf][nf][i] = 0.0f;

    for (int k0 = 0; k0 < K; k0 += BK) {
#pragma unroll
        for (int it = 0; it < 4; it++) {
            int f4 = tid + it * 256;
            int row = f4 >> 3;
            int kg = (f4 & 7) << 2;
            float4 v = make_float4(0.f, 0.f, 0.f, 0.f);
            if (m0 + row < N) v = *(const float4*)(X + (size_t)(m0 + row) * K + k0 + kg);
            float4 hi, lo;
            split4(v, hi, lo);
            *(float4*)(As_hi + row * AP + kg) = hi;
            *(float4*)(As_lo + row * AP + kg) = lo;
        }
        constexpr int WIT = FO * BK / 4 / 256;
#pragma unroll
        for (int it = 0; it < WIT; it++) {
            int f4 = tid + it * 256;
            int n = f4 >> 3;
            int kg = (f4 & 7) << 2;
            *(float4*)(Ws_hi + n * AP + kg) = *(const float4*)(Whi_t + (size_t)n * K + k0 + kg);
            *(float4*)(Ws_lo + n * AP + kg) = *(const float4*)(Wlo_t + (size_t)n * K + k0 + kg);
        }
        __syncthreads();

#pragma unroll
        for (int ks = 0; ks < 4; ks++) {
            const int kb = ks * 8;
            uint32_t ah[2][4], al[2][4];
#pragma unroll
            for (int mf = 0; mf < 2; mf++) {
                uint32_t off = ((warp_m + mf * 16 + (a_grp & 1) * 8 + a_r8) * AP
                                + kb + (a_grp >> 1) * 4) * 4;
                ldsm_x4(ah[mf], as_hi_b + off);
                ldsm_x4(al[mf], as_lo_b + off);
            }
#pragma unroll
            for (int nf = 0; nf < NF; nf++) {
                uint32_t boff = ((warp_n + nf * 8 + b_r8) * AP + kb + b_half * 4) * 4;
                uint32_t bh[2], bl[2];
                ldsm_x2(bh, ws_hi_b + boff);
                ldsm_x2(bl, ws_lo_b + boff);
#pragma unroll
                for (int mf = 0; mf < 2; mf++) {
                    mma_tf32(acc[mf][nf], ah[mf], bh);
                    mma_tf32(acc[mf][nf], al[mf], bh);
                    mma_tf32(acc[mf][nf], ah[mf], bl);
                }
            }
        }
        __syncthreads();
    }

#pragma unroll
    for (int mf = 0; mf < 2; mf++) {
        int r0 = m0 + warp_m + mf * 16 + g;
#pragma unroll
        for (int nf = 0; nf < NF; nf++) {
            int col = warp_n + nf * 8 + 2 * t;
            if constexpr (H16) {
                __half* H = (__half*)Hout;
                if (r0 < N)
                    *(__half2*)(H + (size_t)r0 * FO + col) =
                        __floats2half2_rn(acc[mf][nf][0], acc[mf][nf][1]);
                if (r0 + 8 < N)
                    *(__half2*)(H + (size_t)(r0 + 8) * FO + col) =
                        __floats2half2_rn(acc[mf][nf][2], acc[mf][nf][3]);
            } else {
                float* H = (float*)Hout;
                if (r0 < N)
                    *(float2*)(H + (size_t)r0 * FO + col) =
                        make_float2(acc[mf][nf][0], acc[mf][nf][1]);
                if (r0 + 8 < N)
                    *(float2*)(H + (size_t)(r0 + 8) * FO + col) =
                        make_float2(acc[mf][nf][2], acc[mf][nf][3]);
            }
        }
    }
}

// ---------------- fused CSR gather (fp16 H) + self-loop + bias + ReLU ----------------
__global__ __launch_bounds__(256)
void k_agg128h(const __half* __restrict__ H, const float* __restrict__ bias,
               float* __restrict__ Out, int N) {
    int node = (blockIdx.x * blockDim.x + threadIdx.x) >> 5;
    if (node >= N) return;
    int lane = threadIdx.x & 31;
    int beg = g_rowptr[node];
    int end = g_rowptr[node + 1];

    float4 acc = make_float4(0.f, 0.f, 0.f, 0.f);
    int j = beg;
    for (; j + 1 < end; j += 2) {
        int2 p0 = __ldg(&g_epack[j]);
        int2 p1 = __ldg(&g_epack[j + 1]);
        float v0 = __int_as_float(p0.y);
        float v1 = __int_as_float(p1.y);
        uint2 r0 = *(const uint2*)(H + (size_t)p0.x * 128 + lane * 4);
        uint2 r1 = *(const uint2*)(H + (size_t)p1.x * 128 + lane * 4);
        float2 a0 = __half22float2(*(__half2*)&r0.x);
        float2 a1 = __half22float2(*(__half2*)&r0.y);
        float2 c0 = __half22float2(*(__half2*)&r1.x);
        float2 c1 = __half22float2(*(__half2*)&r1.y);
        acc.x += v0 * a0.x + v1 * c0.x;
        acc.y += v0 * a0.y + v1 * c0.y;
        acc.z += v0 * a1.x + v1 * c1.x;
        acc.w += v0 * a1.y + v1 * c1.y;
    }
    if (j < end) {
        int2 p0 = __ldg(&g_epack[j]);
        float v0 = __int_as_float(p0.y);
        uint2 r0 = *(const uint2*)(H + (size_t)p0.x * 128 + lane * 4);
        float2 a0 = __half22float2(*(__half2*)&r0.x);
        float2 a1 = __half22float2(*(__half2*)&r0.y);
        acc.x += v0 * a0.x; acc.y += v0 * a0.y;
        acc.z += v0 * a1.x; acc.w += v0 * a1.y;
    }

    float d = g_dis[node];
    float dd = d * d;
    uint2 rs = *(const uint2*)(H + (size_t)node * 128 + lane * 4);
    float2 s0 = __half22float2(*(__half2*)&rs.x);
    float2 s1 = __half22float2(*(__half2*)&rs.y);
    float4 b = *(const float4*)(bias + lane * 4);
    float4 o;
    o.x = fmaf(d, acc.x, fmaf(dd, s0.x, b.x));
    o.y = fmaf(d, acc.y, fmaf(dd, s0.y, b.y));
    o.z = fmaf(d, acc.z, fmaf(dd, s1.x, b.z));
    o.w = fmaf(d, acc.w, fmaf(dd, s1.y, b.w));
    o.x = fmaxf(o.x, 0.f); o.y = fmaxf(o.y, 0.f);
    o.z = fmaxf(o.z, 0.f); o.w = fmaxf(o.w, 0.f);
    *(float4*)(Out + (size_t)node * 128 + lane * 4) = o;
}

// fp32 H, 64-wide, no ReLU (final layer)
__global__ __launch_bounds__(256)
void k_agg64(const float* __restrict__ H, const float* __restrict__ bias,
             float* __restrict__ Out, int N) {
    int node = (blockIdx.x * blockDim.x + threadIdx.x) >> 5;
    if (node >= N) return;
    int lane = threadIdx.x & 31;
    int beg = g_rowptr[node];
    int end = g_rowptr[node + 1];

    float2 acc = make_float2(0.f, 0.f);
    int j = beg;
    for (; j + 1 < end; j += 2) {
        int2 p0 = __ldg(&g_epack[j]);
        int2 p1 = __ldg(&g_epack[j + 1]);
        float v0 = __int_as_float(p0.y);
        float v1 = __int_as_float(p1.y);
        float2 h0 = *(const float2*)(H + (size_t)p0.x * 64 + lane * 2);
        float2 h1 = *(const float2*)(H + (size_t)p1.x * 64 + lane * 2);
        acc.x += v0 * h0.x + v1 * h1.x;
        acc.y += v0 * h0.y + v1 * h1.y;
    }
    if (j < end) {
        int2 p0 = __ldg(&g_epack[j]);
        float v0 = __int_as_float(p0.y);
        float2 h0 = *(const float2*)(H + (size_t)p0.x * 64 + lane * 2);
        acc.x += v0 * h0.x; acc.y += v0 * h0.y;
    }

    float d = g_dis[node];
    float dd = d * d;
    float2 hs = *(const float2*)(H + (size_t)node * 64 + lane * 2);
    float2 b = *(const float2*)(bias + lane * 2);
    float2 o;
    o.x = fmaf(d, acc.x, fmaf(dd, hs.x, b.x));
    o.y = fmaf(d, acc.y, fmaf(dd, hs.y, b.y));
    *(float2*)(Out + (size_t)node * 64 + lane * 2) = o;
}

// ---------------- launch ----------------
extern "C" void kernel_launch(void* const* d_in, const int* in_sizes, int n_in,
                              void* d_out, int out_size) {
    const float* x  = (const float*)d_in[0];
    const int*   ei = (const int*)d_in[1];
    const float* ew = (const float*)d_in[2];
    const float* W1 = (const float*)d_in[3];
    const float* b1 = (const float*)d_in[4];
    const float* W2 = (const float*)d_in[5];
    const float* b2 = (const float*)d_in[6];
    const float* W3 = (const float*)d_in[7];
    const float* b3 = (const float*)d_in[8];
    float* out = (float*)d_out;

    const int N = in_sizes[0] / 256;
    const int E = in_sizes[2];
    const int* src = ei;
    const int* dst = ei + E;

    __half* ghh; cudaGetSymbolAddress((void**)&ghh, g_hh);
    float* gh;  cudaGetSymbolAddress((void**)&gh,  g_h);
    float* ga;  cudaGetSymbolAddress((void**)&ga,  g_a);
    float* gb;  cudaGetSymbolAddress((void**)&gb,  g_b2);
    float* gdeg; cudaGetSymbolAddress((void**)&gdeg, g_deg);
    int*   gcnt; cudaGetSymbolAddress((void**)&gcnt, g_cnt);
    float* w1h; cudaGetSymbolAddress((void**)&w1h, g_w1hi);
    float* w1l; cudaGetSymbolAddress((void**)&w1l, g_w1lo);
    float* w2h; cudaGetSymbolAddress((void**)&w2h, g_w2hi);
    float* w2l; cudaGetSymbolAddress((void**)&w2l, g_w2lo);
    float* w3h; cudaGetSymbolAddress((void**)&w3h, g_w3hi);
    float* w3l; cudaGetSymbolAddress((void**)&w3l, g_w3lo);

    const int T = 256;
    auto cdiv = [](int a, int b) { return (a + b - 1) / b; };
    const int nchunks = cdiv(N, CHUNK);

    const int smem128 = (2 * 128 * 36 + 2 * 128 * 36) * 4;
    const int smem64  = (2 * 128 * 36 + 2 * 64 * 36) * 4;
    cudaFuncSetAttribute(k_gemm_tc<256, 128, true>,  cudaFuncAttributeMaxDynamicSharedMemorySize, smem128);
    cudaFuncSetAttribute(k_gemm_tc<128, 128, true>,  cudaFuncAttributeMaxDynamicSharedMemorySize, smem128);
    cudaFuncSetAttribute(k_gemm_tc<128, 64, false>,  cudaFuncAttributeMaxDynamicSharedMemorySize, smem64);

    static cudaStream_t s2 = nullptr;
    static cudaEvent_t evF = nullptr, evJ = nullptr;
    if (s2 == nullptr) {
        cudaStreamCreateWithFlags(&s2, cudaStreamNonBlocking);
        cudaEventCreateWithFlags(&evF, cudaEventDisableTiming);
        cudaEventCreateWithFlags(&evJ, cudaEventDisableTiming);
    }

    // ---- fork: CSR build on s2, weights+GEMM1 on default ----
    cudaEventRecord(evF, 0);
    cudaStreamWaitEvent(s2, evF, 0);

    cudaMemsetAsync(gdeg, 0, N * sizeof(float), s2);
    cudaMemsetAsync(gcnt, 0, N * sizeof(int), s2);
    k_hist<<<cdiv(E, T), T, 0, s2>>>(dst, ew, E);
    k_scanA<<<nchunks, CHUNK, 0, s2>>>(N);
    k_scanC<<<cdiv(N, T), T, 0, s2>>>(N, E, nchunks);
    k_fill<<<cdiv(E, T), T, 0, s2>>>(src, dst, ew, E);

    const int wtot = 256 * 128 + 128 * 128 + 128 * 64;
    k_splitW<<<cdiv(wtot, T), T>>>(W1, W2, W3);

    const int gemm_blocks = cdiv(N, 128);
    const int agg_blocks = cdiv(N * 32, T);

    k_gemm_tc<256, 128, true><<<gemm_blocks, 256, smem128>>>(x, w1h, w1l, ghh, N);

    // ---- join ----
    cudaEventRecord(evJ, s2);
    cudaStreamWaitEvent(0, evJ, 0);

    k_agg128h<<<agg_blocks, T>>>(ghh, b1, ga, N);

    k_gemm_tc<128, 128, true><<<gemm_blocks, 256, smem128>>>(ga, w2h, w2l, ghh, N);
    k_agg128h<<<agg_blocks, T>>>(ghh, b2, gb, N);

    k_gemm_tc<128, 64, false><<<gemm_blocks, 256, smem64>>>(gb, w3h, w3l, gh, N);
    k_agg64<<<agg_blocks, T>>>(gh, b3, out, N);
}

// round 13
// speedup vs baseline: 3.0240x; 1.2358x over previous
#include <cuda_runtime.h>
#include <cuda_bf16.h>
#include <cuda_fp16.h>
#include <cstdint>

#define MAX_N 50000
#define MAX_E 800000
#define CHUNK 256
#define MAX_CHUNKS ((MAX_N + CHUNK - 1) / CHUNK)

// ---------------- device scratch (no allocation allowed) ----------------
__device__ float g_deg[MAX_N];
__device__ float g_dis[MAX_N];
__device__ int   g_cnt[MAX_N];
__device__ int   g_rowptr[MAX_N + 1];
__device__ int   g_cur[MAX_N];
__device__ int   g_csum[MAX_CHUNKS];
__device__ int2  g_epack[MAX_E];                 // (src, val bits)
__device__ __half g_hh[(size_t)MAX_N * 128];     // fp16 GEMM output (all layers)
__device__ float g_a[(size_t)MAX_N * 128];
__device__ float g_b2[(size_t)MAX_N * 128];
// pre-split transposed weights: [FO][K] layout, hi/lo bf16 parts
__device__ __nv_bfloat16 g_w1hi[128 * 256], g_w1lo[128 * 256];
__device__ __nv_bfloat16 g_w2hi[128 * 128], g_w2lo[128 * 128];
__device__ __nv_bfloat16 g_w3hi[64 * 128],  g_w3lo[64 * 128];

// ---------------- bf16 helpers ----------------
__device__ __forceinline__ void mma_bf16(float* c, const uint32_t* a, const uint32_t* b) {
    asm volatile("mma.sync.aligned.m16n8k16.row.col.f32.bf16.bf16.f32 "
                 "{%0,%1,%2,%3}, {%4,%5,%6,%7}, {%8,%9}, {%0,%1,%2,%3};"
                 : "+f"(c[0]), "+f"(c[1]), "+f"(c[2]), "+f"(c[3])
                 : "r"(a[0]), "r"(a[1]), "r"(a[2]), "r"(a[3]),
                   "r"(b[0]), "r"(b[1]));
}

__device__ __forceinline__ void ldsm_x4(uint32_t* r, uint32_t saddr) {
    asm volatile("ldmatrix.sync.aligned.m8n8.x4.shared.b16 {%0,%1,%2,%3}, [%4];"
                 : "=r"(r[0]), "=r"(r[1]), "=r"(r[2]), "=r"(r[3]) : "r"(saddr));
}

__device__ __forceinline__ void ldsm_x2(uint32_t* r, uint32_t saddr) {
    asm volatile("ldmatrix.sync.aligned.m8n8.x2.shared.b16 {%0,%1}, [%2];"
                 : "=r"(r[0]), "=r"(r[1]) : "r"(saddr));
}

// ---------------- weight pre-split (transposed, bf16 hi/lo) ----------------
__global__ void k_splitW(const float* __restrict__ W1, const float* __restrict__ W2,
                         const float* __restrict__ W3) {
    int i = blockIdx.x * blockDim.x + threadIdx.x;
    const int n1 = 256 * 128, n2 = 128 * 128, n3 = 128 * 64;
    float v; __nv_bfloat16* ph; __nv_bfloat16* pl;
    if (i < n1) {
        int k = i / 128, n = i % 128;
        v = W1[i]; ph = &g_w1hi[n * 256 + k]; pl = &g_w1lo[n * 256 + k];
    } else if (i < n1 + n2) {
        int j = i - n1; int k = j / 128, n = j % 128;
        v = W2[j]; ph = &g_w2hi[n * 128 + k]; pl = &g_w2lo[n * 128 + k];
    } else if (i < n1 + n2 + n3) {
        int j = i - n1 - n2; int k = j / 64, n = j % 64;
        v = W3[j]; ph = &g_w3hi[n * 128 + k]; pl = &g_w3lo[n * 128 + k];
    } else return;
    __nv_bfloat16 hi = __float2bfloat16_rn(v);
    *ph = hi;
    *pl = __float2bfloat16_rn(v - __bfloat162float(hi));
}

// ---------------- CSR precompute ----------------
__global__ void k_hist(const int* __restrict__ dst, const float* __restrict__ w, int E) {
    int i = blockIdx.x * blockDim.x + threadIdx.x;
    if (i < E) {
        int d = dst[i];
        atomicAdd(&g_deg[d], w[i]);
        atomicAdd(&g_cnt[d], 1);
    }
}

__global__ void k_scanA(int N) {
    __shared__ int s[CHUNK];
    int t = threadIdx.x;
    int i = blockIdx.x * CHUNK + t;
    int v = (i < N) ? g_cnt[i] : 0;
    s[t] = v;
    __syncthreads();
#pragma unroll
    for (int off = 1; off < CHUNK; off <<= 1) {
        int x = (t >= off) ? s[t - off] : 0;
        __syncthreads();
        s[t] += x;
        __syncthreads();
    }
    if (i < N) g_rowptr[i] = s[t] - v;
    if (t == CHUNK - 1) g_csum[blockIdx.x] = s[t];
}

__global__ void k_scanC(int N, int E, int nchunks) {
    __shared__ int sc[CHUNK];
    int t = threadIdx.x;
    int v = (t < nchunks) ? g_csum[t] : 0;
    sc[t] = v;
    __syncthreads();
#pragma unroll
    for (int off = 1; off < CHUNK; off <<= 1) {
        int x = (t >= off) ? sc[t - off] : 0;
        __syncthreads();
        sc[t] += x;
        __syncthreads();
    }
    int i = blockIdx.x * blockDim.x + t;
    if (i < N) {
        int c = i >> 8;
        int off = (c == 0) ? 0 : sc[c - 1];
        int r = g_rowptr[i] + off;
        g_rowptr[i] = r;
        g_cur[i] = r;
        g_dis[i] = rsqrtf(g_deg[i] + 1.0f);   // self-loop weight 1
    }
    if (i == 0) g_rowptr[N] = E;
}

__global__ void k_fill(const int* __restrict__ src, const int* __restrict__ dst,
                       const float* __restrict__ w, int E) {
    int e = blockIdx.x * blockDim.x + threadIdx.x;
    if (e >= E) return;
    int d = dst[e];
    int s = src[e];
    int pos = atomicAdd(&g_cur[d], 1);
    int2 pk;
    pk.x = s;
    pk.y = __float_as_int(w[e] * g_dis[s]);   // dis[dst] factored into epilogue
    g_epack[pos] = pk;
}

// ---------------- 3-term bf16 tensor-core GEMM (m16n8k16) ----------------
// H[N,FO] = X[N,K] @ W[K,FO]; W pre-split transposed hi/lo bf16 [FO][K]
// Output stored as fp16.
template<int K, int FO>
__global__ __launch_bounds__(256)
void k_gemm_tc(const float* __restrict__ X,
               const __nv_bfloat16* __restrict__ Whi_t,
               const __nv_bfloat16* __restrict__ Wlo_t,
               __half* __restrict__ H, int N) {
    constexpr int BM = 128, BK = 32;
    constexpr int AP = BK + 8;            // 40 bf16 = 80B row stride (16B aligned, conflict-free)
    constexpr int NF = FO / 16;           // n-frags per warp (8 or 4)
    __shared__ __nv_bfloat16 As_hi[BM * AP];
    __shared__ __nv_bfloat16 As_lo[BM * AP];
    __shared__ __nv_bfloat16 Ws_hi[FO * AP];
    __shared__ __nv_bfloat16 Ws_lo[FO * AP];

    const int tid = threadIdx.x;
    const int lane = tid & 31, wid = tid >> 5;
    const int g = lane >> 2, t = lane & 3;
    const int warp_m = (wid & 3) * 32;
    const int warp_n = (wid >> 2) * (FO / 2);
    const int m0 = blockIdx.x * BM;

    const uint32_t as_hi_b = (uint32_t)__cvta_generic_to_shared(As_hi);
    const uint32_t as_lo_b = (uint32_t)__cvta_generic_to_shared(As_lo);
    const uint32_t ws_hi_b = (uint32_t)__cvta_generic_to_shared(Ws_hi);
    const uint32_t ws_lo_b = (uint32_t)__cvta_generic_to_shared(Ws_lo);

    const int a_grp = lane >> 3, a_r8 = lane & 7;      // x4 lane mapping
    const int b_r8 = lane & 7, b_half = (lane >> 3) & 1;   // x2 (lanes 0-15)

    float acc[2][NF][4];
#pragma unroll
    for (int mf = 0; mf < 2; mf++)
#pragma unroll
        for (int nf = 0; nf < NF; nf++)
#pragma unroll
            for (int i = 0; i < 4; i++) acc[mf][nf][i] = 0.0f;

    for (int k0 = 0; k0 < K; k0 += BK) {
        // ---- A tile: 128x32 fp32 -> bf16 hi/lo ----
#pragma unroll
        for (int it = 0; it < 4; it++) {
            int f4 = tid + it * 256;
            int row = f4 >> 3;              // 8 float4 per row
            int kg = (f4 & 7) << 2;
            float4 v = make_float4(0.f, 0.f, 0.f, 0.f);
            if (m0 + row < N) v = *(const float4*)(X + (size_t)(m0 + row) * K + k0 + kg);
            __nv_bfloat16 hx = __float2bfloat16_rn(v.x);
            __nv_bfloat16 hy = __float2bfloat16_rn(v.y);
            __nv_bfloat16 hz = __float2bfloat16_rn(v.z);
            __nv_bfloat16 hw = __float2bfloat16_rn(v.w);
            __nv_bfloat162 hi0, hi1, lo0, lo1;
            hi0.x = hx; hi0.y = hy; hi1.x = hz; hi1.y = hw;
            lo0.x = __float2bfloat16_rn(v.x - __bfloat162float(hx));
            lo0.y = __float2bfloat16_rn(v.y - __bfloat162float(hy));
            lo1.x = __float2bfloat16_rn(v.z - __bfloat162float(hz));
            lo1.y = __float2bfloat16_rn(v.w - __bfloat162float(hw));
            *(__nv_bfloat162*)(As_hi + row * AP + kg) = hi0;
            *(__nv_bfloat162*)(As_hi + row * AP + kg + 2) = hi1;
            *(__nv_bfloat162*)(As_lo + row * AP + kg) = lo0;
            *(__nv_bfloat162*)(As_lo + row * AP + kg + 2) = lo1;
        }
        // ---- W tile: [FO][BK] bf16 from pre-split transposed globals ----
        constexpr int WIT = FO * BK / 8 / 256;   // 8 bf16 per thread-load
#pragma unroll
        for (int it = 0; it < WIT; it++) {
            int u = tid + it * 256;
            int n = u >> 2;                 // 4 x 8-bf16 chunks per row
            int kg = (u & 3) << 3;
            *(uint4*)(Ws_hi + n * AP + kg) = *(const uint4*)(Whi_t + (size_t)n * K + k0 + kg);
            *(uint4*)(Ws_lo + n * AP + kg) = *(const uint4*)(Wlo_t + (size_t)n * K + k0 + kg);
        }
        __syncthreads();

#pragma unroll
        for (int ks = 0; ks < 2; ks++) {
            const int kb = ks * 16;
            uint32_t ah[2][4], al[2][4];
#pragma unroll
            for (int mf = 0; mf < 2; mf++) {
                uint32_t off = ((warp_m + mf * 16 + (a_grp & 1) * 8 + a_r8) * AP
                                + kb + (a_grp >> 1) * 8) * 2;
                ldsm_x4(ah[mf], as_hi_b + off);
                ldsm_x4(al[mf], as_lo_b + off);
            }
#pragma unroll
            for (int nf = 0; nf < NF; nf++) {
                uint32_t boff = ((warp_n + nf * 8 + b_r8) * AP + kb + b_half * 8) * 2;
                uint32_t bh[2], bl[2];
                ldsm_x2(bh, ws_hi_b + boff);
                ldsm_x2(bl, ws_lo_b + boff);
#pragma unroll
                for (int mf = 0; mf < 2; mf++) {
                    mma_bf16(acc[mf][nf], ah[mf], bh);
                    mma_bf16(acc[mf][nf], al[mf], bh);
                    mma_bf16(acc[mf][nf], ah[mf], bl);
                }
            }
        }
        __syncthreads();
    }

#pragma unroll
    for (int mf = 0; mf < 2; mf++) {
        int r0 = m0 + warp_m + mf * 16 + g;
#pragma unroll
        for (int nf = 0; nf < NF; nf++) {
            int col = warp_n + nf * 8 + 2 * t;
            if (r0 < N)
                *(__half2*)(H + (size_t)r0 * FO + col) =
                    __floats2half2_rn(acc[mf][nf][0], acc[mf][nf][1]);
            if (r0 + 8 < N)
                *(__half2*)(H + (size_t)(r0 + 8) * FO + col) =
                    __floats2half2_rn(acc[mf][nf][2], acc[mf][nf][3]);
        }
    }
}

// ---------------- fused CSR gather (fp16 H) + self-loop + bias + ReLU ----------------
__device__ __forceinline__ void acc_row128(float4& acc, float v, uint2 r) {
    float2 a0 = __half22float2(*(__half2*)&r.x);
    float2 a1 = __half22float2(*(__half2*)&r.y);
    acc.x += v * a0.x; acc.y += v * a0.y;
    acc.z += v * a1.x; acc.w += v * a1.y;
}

__global__ __launch_bounds__(256)
void k_agg128h(const __half* __restrict__ H, const float* __restrict__ bias,
               float* __restrict__ Out, int N) {
    int node = (blockIdx.x * blockDim.x + threadIdx.x) >> 5;
    if (node >= N) return;
    int lane = threadIdx.x & 31;
    int beg = g_rowptr[node];
    int end = g_rowptr[node + 1];

    float4 acc = make_float4(0.f, 0.f, 0.f, 0.f);
    int j = beg;
    for (; j + 3 < end; j += 4) {
        int2 p0 = __ldg(&g_epack[j]);
        int2 p1 = __ldg(&g_epack[j + 1]);
        int2 p2 = __ldg(&g_epack[j + 2]);
        int2 p3 = __ldg(&g_epack[j + 3]);
        uint2 r0 = *(const uint2*)(H + (size_t)p0.x * 128 + lane * 4);
        uint2 r1 = *(const uint2*)(H + (size_t)p1.x * 128 + lane * 4);
        uint2 r2 = *(const uint2*)(H + (size_t)p2.x * 128 + lane * 4);
        uint2 r3 = *(const uint2*)(H + (size_t)p3.x * 128 + lane * 4);
        acc_row128(acc, __int_as_float(p0.y), r0);
        acc_row128(acc, __int_as_float(p1.y), r1);
        acc_row128(acc, __int_as_float(p2.y), r2);
        acc_row128(acc, __int_as_float(p3.y), r3);
    }
    for (; j < end; j++) {
        int2 p0 = __ldg(&g_epack[j]);
        uint2 r0 = *(const uint2*)(H + (size_t)p0.x * 128 + lane * 4);
        acc_row128(acc, __int_as_float(p0.y), r0);
    }

    float d = g_dis[node];
    float dd = d * d;
    uint2 rs = *(const uint2*)(H + (size_t)node * 128 + lane * 4);
    float2 s0 = __half22float2(*(__half2*)&rs.x);
    float2 s1 = __half22float2(*(__half2*)&rs.y);
    float4 b = *(const float4*)(bias + lane * 4);
    float4 o;
    o.x = fmaf(d, acc.x, fmaf(dd, s0.x, b.x));
    o.y = fmaf(d, acc.y, fmaf(dd, s0.y, b.y));
    o.z = fmaf(d, acc.z, fmaf(dd, s1.x, b.z));
    o.w = fmaf(d, acc.w, fmaf(dd, s1.y, b.w));
    o.x = fmaxf(o.x, 0.f); o.y = fmaxf(o.y, 0.f);
    o.z = fmaxf(o.z, 0.f); o.w = fmaxf(o.w, 0.f);
    *(float4*)(Out + (size_t)node * 128 + lane * 4) = o;
}

// fp16 H, 64-wide, no ReLU (final layer)
__global__ __launch_bounds__(256)
void k_agg64h(const __half* __restrict__ H, const float* __restrict__ bias,
              float* __restrict__ Out, int N) {
    int node = (blockIdx.x * blockDim.x + threadIdx.x) >> 5;
    if (node >= N) return;
    int lane = threadIdx.x & 31;
    int beg = g_rowptr[node];
    int end = g_rowptr[node + 1];

    float2 acc = make_float2(0.f, 0.f);
    int j = beg;
    for (; j + 3 < end; j += 4) {
        int2 p0 = __ldg(&g_epack[j]);
        int2 p1 = __ldg(&g_epack[j + 1]);
        int2 p2 = __ldg(&g_epack[j + 2]);
        int2 p3 = __ldg(&g_epack[j + 3]);
        float2 h0 = __half22float2(*(const __half2*)(H + (size_t)p0.x * 64 + lane * 2));
        float2 h1 = __half22float2(*(const __half2*)(H + (size_t)p1.x * 64 + lane * 2));
        float2 h2 = __half22float2(*(const __half2*)(H + (size_t)p2.x * 64 + lane * 2));
        float2 h3 = __half22float2(*(const __half2*)(H + (size_t)p3.x * 64 + lane * 2));
        float v0 = __int_as_float(p0.y), v1 = __int_as_float(p1.y);
        float v2 = __int_as_float(p2.y), v3 = __int_as_float(p3.y);
        acc.x += v0 * h0.x + v1 * h1.x + v2 * h2.x + v3 * h3.x;
        acc.y += v0 * h0.y + v1 * h1.y + v2 * h2.y + v3 * h3.y;
    }
    for (; j < end; j++) {
        int2 p0 = __ldg(&g_epack[j]);
        float v0 = __int_as_float(p0.y);
        float2 h0 = __half22float2(*(const __half2*)(H + (size_t)p0.x * 64 + lane * 2));
        acc.x += v0 * h0.x; acc.y += v0 * h0.y;
    }

    float d = g_dis[node];
    float dd = d * d;
    float2 hs = __half22float2(*(const __half2*)(H + (size_t)node * 64 + lane * 2));
    float2 b = *(const float2*)(bias + lane * 2);
    float2 o;
    o.x = fmaf(d, acc.x, fmaf(dd, hs.x, b.x));
    o.y = fmaf(d, acc.y, fmaf(dd, hs.y, b.y));
    *(float2*)(Out + (size_t)node * 64 + lane * 2) = o;
}

// ---------------- launch ----------------
extern "C" void kernel_launch(void* const* d_in, const int* in_sizes, int n_in,
                              void* d_out, int out_size) {
    const float* x  = (const float*)d_in[0];
    const int*   ei = (const int*)d_in[1];
    const float* ew = (const float*)d_in[2];
    const float* W1 = (const float*)d_in[3];
    const float* b1 = (const float*)d_in[4];
    const float* W2 = (const float*)d_in[5];
    const float* b2 = (const float*)d_in[6];
    const float* W3 = (const float*)d_in[7];
    const float* b3 = (const float*)d_in[8];
    float* out = (float*)d_out;

    const int N = in_sizes[0] / 256;
    const int E = in_sizes[2];
    const int* src = ei;
    const int* dst = ei + E;

    __half* ghh; cudaGetSymbolAddress((void**)&ghh, g_hh);
    float* ga;  cudaGetSymbolAddress((void**)&ga,  g_a);
    float* gb;  cudaGetSymbolAddress((void**)&gb,  g_b2);
    float* gdeg; cudaGetSymbolAddress((void**)&gdeg, g_deg);
    int*   gcnt; cudaGetSymbolAddress((void**)&gcnt, g_cnt);
    __nv_bfloat16* w1h; cudaGetSymbolAddress((void**)&w1h, g_w1hi);
    __nv_bfloat16* w1l; cudaGetSymbolAddress((void**)&w1l, g_w1lo);
    __nv_bfloat16* w2h; cudaGetSymbolAddress((void**)&w2h, g_w2hi);
    __nv_bfloat16* w2l; cudaGetSymbolAddress((void**)&w2l, g_w2lo);
    __nv_bfloat16* w3h; cudaGetSymbolAddress((void**)&w3h, g_w3hi);
    __nv_bfloat16* w3l; cudaGetSymbolAddress((void**)&w3l, g_w3lo);

    const int T = 256;
    auto cdiv = [](int a, int b) { return (a + b - 1) / b; };
    const int nchunks = cdiv(N, CHUNK);

    static cudaStream_t s2 = nullptr;
    static cudaEvent_t evF = nullptr, evJ = nullptr;
    if (s2 == nullptr) {
        cudaStreamCreateWithFlags(&s2, cudaStreamNonBlocking);
        cudaEventCreateWithFlags(&evF, cudaEventDisableTiming);
        cudaEventCreateWithFlags(&evJ, cudaEventDisableTiming);
    }

    // ---- fork: CSR build on s2, weights+GEMM1 on default ----
    cudaEventRecord(evF, 0);
    cudaStreamWaitEvent(s2, evF, 0);

    cudaMemsetAsync(gdeg, 0, N * sizeof(float), s2);
    cudaMemsetAsync(gcnt, 0, N * sizeof(int), s2);
    k_hist<<<cdiv(E, T), T, 0, s2>>>(dst, ew, E);
    k_scanA<<<nchunks, CHUNK, 0, s2>>>(N);
    k_scanC<<<cdiv(N, T), T, 0, s2>>>(N, E, nchunks);
    k_fill<<<cdiv(E, T), T, 0, s2>>>(src, dst, ew, E);

    const int wtot = 256 * 128 + 128 * 128 + 128 * 64;
    k_splitW<<<cdiv(wtot, T), T>>>(W1, W2, W3);

    const int gemm_blocks = cdiv(N, 128);
    const int agg_blocks = cdiv(N * 32, T);

    k_gemm_tc<256, 128><<<gemm_blocks, 256>>>(x, w1h, w1l, ghh, N);

    // ---- join ----
    cudaEventRecord(evJ, s2);
    cudaStreamWaitEvent(0, evJ, 0);

    k_agg128h<<<agg_blocks, T>>>(ghh, b1, ga, N);

    k_gemm_tc<128, 128><<<gemm_blocks, 256>>>(ga, w2h, w2l, ghh, N);
    k_agg128h<<<agg_blocks, T>>>(ghh, b2, gb, N);

    k_gemm_tc<128, 64><<<gemm_blocks, 256>>>(gb, w3h, w3l, ghh, N);
    k_agg64h<<<agg_blocks, T>>>(ghh, b3, out, N);
}